// round 1
// baseline (speedup 1.0000x reference)
#include <cuda_runtime.h>
#include <math.h>
#include <stdint.h>

// Problem constants
#define BTC   16          // B*T
#define SEQ   1024        // H*W
#define DMODEL 768
#define NHEADS 12
#define HDIM  64
#define MROWS (BTC * SEQ)     // 16384
#define QKVN  (3 * DMODEL)    // 2304

// Device scratch (allocation-guard-safe: static device globals)
__device__ float g_qkv[(size_t)MROWS * QKVN];   // [16384, 2304]
__device__ float g_o[(size_t)MROWS * DMODEL];   // [16384, 768]
__device__ float g_cos[SEQ * 32];
__device__ float g_sin[SEQ * 32];

// ---------------------------------------------------------------------------
// RoPE cos/sin table: 1024 positions x 32 pair-frequencies
// half = HDIM/4 = 16; p<16 -> h-axis, p>=16 -> w-axis; inv_freq = 10000^(-j/16)
// ---------------------------------------------------------------------------
__global__ void rope_table_kernel() {
    int idx = blockIdx.x * blockDim.x + threadIdx.x;
    if (idx >= SEQ * 32) return;
    int s = idx >> 5;
    int p = idx & 31;
    int hi = s >> 5;
    int wi = s & 31;
    float pos = (p < 16) ? (float)hi : (float)wi;
    int j = p & 15;
    // log2(10000)/16
    float inv = exp2f(-(float)j * 0.8304820236903231f);
    float th = pos * inv;
    g_cos[idx] = cosf(th);
    g_sin[idx] = sinf(th);
}

// ---------------------------------------------------------------------------
// Apply RoPE in place to q and k thirds of g_qkv.
// grid = 16384 rows, block = 384 threads (12 heads * 32 pairs)
// ---------------------------------------------------------------------------
__global__ void rope_apply_kernel() {
    int n = blockIdx.x;               // row in [0, 16384)
    int t = threadIdx.x;              // 0..383
    int s = n & (SEQ - 1);
    int hh = t >> 5;                  // head
    int p  = t & 31;                  // pair index
    float c  = g_cos[(s << 5) + p];
    float sn = g_sin[(s << 5) + p];

    float* q = g_qkv + (size_t)n * QKVN + hh * HDIM + 2 * p;
    float2 xq = *(float2*)q;
    float2 oq;
    oq.x = xq.x * c - xq.y * sn;
    oq.y = xq.y * c + xq.x * sn;
    *(float2*)q = oq;

    float* k = q + DMODEL;
    float2 xk = *(float2*)k;
    float2 ok;
    ok.x = xk.x * c - xk.y * sn;
    ok.y = xk.y * c + xk.x * sn;
    *(float2*)k = ok;
}

// ---------------------------------------------------------------------------
// Tiled fp32 GEMM: C[M,N] = A[M,K] * B[N,K]^T (+ optional bias[N])
// BM=BN=128, BK=16, 256 threads, 8x8 microtile per thread.
// All problem dims divide the tiles exactly (no bounds checks).
// ---------------------------------------------------------------------------
__global__ __launch_bounds__(256, 2)
void sgemm_nt(const float* __restrict__ A, const float* __restrict__ B,
              float* __restrict__ C, int M, int N, int K,
              const float* __restrict__ bias)
{
    __shared__ float As[16][128];
    __shared__ float Bs[16][128];

    const int bm = blockIdx.y * 128;
    const int bn = blockIdx.x * 128;
    const int t  = threadIdx.x;
    const int tx = t & 15;          // n microtile
    const int ty = t >> 4;          // m microtile

    const int lr = t >> 2;          // 0..63 (load row)
    const int lk = (t & 3) * 4;     // 0,4,8,12 (load k offset)

    float acc[8][8];
#pragma unroll
    for (int i = 0; i < 8; i++)
#pragma unroll
        for (int j = 0; j < 8; j++) acc[i][j] = 0.0f;

    for (int k0 = 0; k0 < K; k0 += 16) {
        float4 a0 = *(const float4*)&A[(size_t)(bm + lr)      * K + k0 + lk];
        float4 a1 = *(const float4*)&A[(size_t)(bm + lr + 64) * K + k0 + lk];
        float4 b0 = *(const float4*)&B[(size_t)(bn + lr)      * K + k0 + lk];
        float4 b1 = *(const float4*)&B[(size_t)(bn + lr + 64) * K + k0 + lk];

        __syncthreads();
        As[lk + 0][lr] = a0.x; As[lk + 1][lr] = a0.y;
        As[lk + 2][lr] = a0.z; As[lk + 3][lr] = a0.w;
        As[lk + 0][lr + 64] = a1.x; As[lk + 1][lr + 64] = a1.y;
        As[lk + 2][lr + 64] = a1.z; As[lk + 3][lr + 64] = a1.w;
        Bs[lk + 0][lr] = b0.x; Bs[lk + 1][lr] = b0.y;
        Bs[lk + 2][lr] = b0.z; Bs[lk + 3][lr] = b0.w;
        Bs[lk + 0][lr + 64] = b1.x; Bs[lk + 1][lr + 64] = b1.y;
        Bs[lk + 2][lr + 64] = b1.z; Bs[lk + 3][lr + 64] = b1.w;
        __syncthreads();

#pragma unroll
        for (int k = 0; k < 16; k++) {
            float a[8], b[8];
            *(float4*)&a[0] = *(const float4*)&As[k][ty * 8];
            *(float4*)&a[4] = *(const float4*)&As[k][ty * 8 + 4];
            *(float4*)&b[0] = *(const float4*)&Bs[k][tx * 8];
            *(float4*)&b[4] = *(const float4*)&Bs[k][tx * 8 + 4];
#pragma unroll
            for (int i = 0; i < 8; i++)
#pragma unroll
                for (int j = 0; j < 8; j++)
                    acc[i][j] = fmaf(a[i], b[j], acc[i][j]);
        }
    }

#pragma unroll
    for (int i = 0; i < 8; i++) {
        int row = bm + ty * 8 + i;
#pragma unroll
        for (int j4 = 0; j4 < 2; j4++) {
            int col = bn + tx * 8 + j4 * 4;
            float4 r4;
            r4.x = acc[i][j4 * 4 + 0];
            r4.y = acc[i][j4 * 4 + 1];
            r4.z = acc[i][j4 * 4 + 2];
            r4.w = acc[i][j4 * 4 + 3];
            if (bias) {
                float4 bv = *(const float4*)&bias[col];
                r4.x += bv.x; r4.y += bv.y; r4.z += bv.z; r4.w += bv.w;
            }
            *(float4*)&C[(size_t)row * N + col] = r4;
        }
    }
}

// ---------------------------------------------------------------------------
// Flash-style attention.
// grid = (SEQ/64 q-tiles, BTC*NHEADS), block = 256 threads.
// Thread t: row r = t/4 of the 64-row q tile, col group cg = t%4
// (16 of 64 columns). Online softmax; P tile reuses the K smem buffer.
// Q is pre-scaled by 1/sqrt(64) at load. Exactly 48KB static smem.
// ---------------------------------------------------------------------------
__global__ __launch_bounds__(256)
void attn_kernel()
{
    __shared__ float Qs[64][64];
    __shared__ float KPs[64][64];   // K tile, then reused to hold P
    __shared__ float Vs[64][64];

    const int bh = blockIdx.y;           // 0..191
    const int bt = bh / NHEADS;
    const int hh = bh % NHEADS;
    const int q0 = blockIdx.x * 64;
    const int t  = threadIdx.x;
    const int r  = t >> 2;               // 0..63
    const int cg = t & 3;                // 0..3

    const float* qbase = g_qkv + (size_t)bt * SEQ * QKVN + hh * HDIM;
    const float* kbase = qbase + DMODEL;
    const float* vbase = qbase + 2 * DMODEL;

    // load Q tile (scaled)
    {
        const int lr = t >> 2;
        const int lc = (t & 3) * 16;
#pragma unroll
        for (int j = 0; j < 4; j++) {
            float4 v = *(const float4*)&qbase[(size_t)(q0 + lr) * QKVN + lc + j * 4];
            v.x *= 0.125f; v.y *= 0.125f; v.z *= 0.125f; v.w *= 0.125f;
            *(float4*)&Qs[lr][lc + j * 4] = v;
        }
    }

    float m = -1e30f;
    float l = 0.0f;
    float oacc[16];
#pragma unroll
    for (int j = 0; j < 16; j++) oacc[j] = 0.0f;

    for (int kt = 0; kt < SEQ / 64; kt++) {
        __syncthreads();   // prior P reads complete before overwriting KPs/Vs
        {
            const int lr = t >> 2;
            const int lc = (t & 3) * 16;
#pragma unroll
            for (int j = 0; j < 4; j++) {
                *(float4*)&KPs[lr][lc + j * 4] =
                    *(const float4*)&kbase[(size_t)(kt * 64 + lr) * QKVN + lc + j * 4];
                *(float4*)&Vs[lr][lc + j * 4] =
                    *(const float4*)&vbase[(size_t)(kt * 64 + lr) * QKVN + lc + j * 4];
            }
        }
        __syncthreads();

        // S = Q K^T : this thread computes row r, cols [cg*16, cg*16+16)
        float sacc[16];
#pragma unroll
        for (int i = 0; i < 16; i++) sacc[i] = 0.0f;
#pragma unroll 4
        for (int d4 = 0; d4 < 16; d4++) {
            float4 qv = *(const float4*)&Qs[r][d4 * 4];
#pragma unroll
            for (int i = 0; i < 16; i++) {
                float4 kv = *(const float4*)&KPs[cg * 16 + i][d4 * 4];
                sacc[i] = fmaf(qv.x, kv.x, sacc[i]);
                sacc[i] = fmaf(qv.y, kv.y, sacc[i]);
                sacc[i] = fmaf(qv.z, kv.z, sacc[i]);
                sacc[i] = fmaf(qv.w, kv.w, sacc[i]);
            }
        }

        // row max across this thread's 16 + the other 3 threads of the row
        float mt = sacc[0];
#pragma unroll
        for (int i = 1; i < 16; i++) mt = fmaxf(mt, sacc[i]);
        mt = fmaxf(mt, __shfl_xor_sync(0xffffffffu, mt, 1));
        mt = fmaxf(mt, __shfl_xor_sync(0xffffffffu, mt, 2));
        float mnew  = fmaxf(m, mt);
        float alpha = __expf(m - mnew);

        float psum = 0.0f;
#pragma unroll
        for (int i = 0; i < 16; i++) {
            float p = __expf(sacc[i] - mnew);
            sacc[i] = p;
            psum += p;
        }
        psum += __shfl_xor_sync(0xffffffffu, psum, 1);
        psum += __shfl_xor_sync(0xffffffffu, psum, 2);
        l = l * alpha + psum;
        m = mnew;
#pragma unroll
        for (int j = 0; j < 16; j++) oacc[j] *= alpha;

        __syncthreads();   // all K reads done -> safe to overwrite with P
#pragma unroll
        for (int i4 = 0; i4 < 4; i4++) {
            float4 p4;
            p4.x = sacc[i4 * 4 + 0];
            p4.y = sacc[i4 * 4 + 1];
            p4.z = sacc[i4 * 4 + 2];
            p4.w = sacc[i4 * 4 + 3];
            *(float4*)&KPs[r][cg * 16 + i4 * 4] = p4;
        }
        __syncthreads();

        // O[r, cg*16 + j] += sum_c P[r][c] * V[c][cg*16 + j]
#pragma unroll 8
        for (int c = 0; c < 64; c++) {
            float p = KPs[r][c];
#pragma unroll
            for (int j4 = 0; j4 < 4; j4++) {
                float4 vv = *(const float4*)&Vs[c][cg * 16 + j4 * 4];
                oacc[j4 * 4 + 0] = fmaf(p, vv.x, oacc[j4 * 4 + 0]);
                oacc[j4 * 4 + 1] = fmaf(p, vv.y, oacc[j4 * 4 + 1]);
                oacc[j4 * 4 + 2] = fmaf(p, vv.z, oacc[j4 * 4 + 2]);
                oacc[j4 * 4 + 3] = fmaf(p, vv.w, oacc[j4 * 4 + 3]);
            }
        }
    }

    const float inv = 1.0f / l;
    float* orow = g_o + (size_t)(bt * SEQ + q0 + r) * DMODEL + hh * HDIM + cg * 16;
#pragma unroll
    for (int j4 = 0; j4 < 4; j4++) {
        float4 r4;
        r4.x = oacc[j4 * 4 + 0] * inv;
        r4.y = oacc[j4 * 4 + 1] * inv;
        r4.z = oacc[j4 * 4 + 2] * inv;
        r4.w = oacc[j4 * 4 + 3] * inv;
        *(float4*)&orow[j4 * 4] = r4;
    }
}

// ---------------------------------------------------------------------------
extern "C" void kernel_launch(void* const* d_in, const int* in_sizes, int n_in,
                              void* d_out, int out_size)
{
    const float* x     = (const float*)d_in[0];   // [2,8,32,32,768]
    const float* w_qkv = (const float*)d_in[1];   // [2304, 768]
    const float* w_out = (const float*)d_in[2];   // [768, 768]
    const float* b_out = (const float*)d_in[3];   // [768]
    float* out = (float*)d_out;

    float* qkv; float* o;
    cudaGetSymbolAddress((void**)&qkv, g_qkv);
    cudaGetSymbolAddress((void**)&o, g_o);

    rope_table_kernel<<<(SEQ * 32 + 255) / 256, 256>>>();

    // qkv = x @ w_qkv^T
    sgemm_nt<<<dim3(QKVN / 128, MROWS / 128), 256>>>(
        x, w_qkv, qkv, MROWS, QKVN, DMODEL, nullptr);

    rope_apply_kernel<<<MROWS, 384>>>();

    attn_kernel<<<dim3(SEQ / 64, BTC * NHEADS), 256>>>();

    // out = o @ w_out^T + b_out
    sgemm_nt<<<dim3(DMODEL / 128, MROWS / 128), 256>>>(
        o, w_out, out, MROWS, DMODEL, DMODEL, b_out);
}

// round 3
// speedup vs baseline: 4.8875x; 4.8875x over previous
#include <cuda_runtime.h>
#include <cuda_bf16.h>
#include <math.h>
#include <stdint.h>

// Problem constants
#define BTC    16
#define SEQ    1024
#define DMODEL 768
#define NHEADS 12
#define HDIM   64
#define MROWS  (BTC * SEQ)     // 16384
#define QKVN   (3 * DMODEL)    // 2304
#define KDIM   768

// Scratch (static device globals: allocation-guard safe)
__device__ float g_qkv[(size_t)MROWS * QKVN];
__device__ float g_o[(size_t)MROWS * DMODEL];
__device__ float g_cos[SEQ * 32];
__device__ float g_sin[SEQ * 32];
__device__ __nv_bfloat16 g_Ah[(size_t)MROWS * KDIM];
__device__ __nv_bfloat16 g_Al[(size_t)MROWS * KDIM];
__device__ __nv_bfloat16 g_Bh[(size_t)QKVN * KDIM];
__device__ __nv_bfloat16 g_Bl[(size_t)QKVN * KDIM];

// ===========================================================================
// Helpers
// ===========================================================================
__device__ __forceinline__ uint32_t smem_u32(const void* p) {
    uint32_t a;
    asm("{ .reg .u64 t; cvta.to.shared.u64 t, %1; cvt.u32.u64 %0, t; }" : "=r"(a) : "l"(p));
    return a;
}
#define CP16(dst, src) \
    asm volatile("cp.async.cg.shared.global [%0], [%1], 16;" :: "r"(dst), "l"(src))
#define CP_COMMIT() asm volatile("cp.async.commit_group;")
#define CP_WAIT(n)  asm volatile("cp.async.wait_group %0;" :: "n"(n))

__device__ __forceinline__ void mma_bf16(float* d, const uint32_t* a, const uint32_t* b) {
    asm volatile(
        "mma.sync.aligned.m16n8k16.row.col.f32.bf16.bf16.f32 "
        "{%0,%1,%2,%3}, {%4,%5,%6,%7}, {%8,%9}, {%0,%1,%2,%3};"
        : "+f"(d[0]), "+f"(d[1]), "+f"(d[2]), "+f"(d[3])
        : "r"(a[0]), "r"(a[1]), "r"(a[2]), "r"(a[3]), "r"(b[0]), "r"(b[1]));
}

// ===========================================================================
// RoPE kernels
// ===========================================================================
__global__ void rope_table_kernel() {
    int idx = blockIdx.x * blockDim.x + threadIdx.x;
    if (idx >= SEQ * 32) return;
    int s = idx >> 5, p = idx & 31;
    float pos = (p < 16) ? (float)(s >> 5) : (float)(s & 31);
    int j = p & 15;
    float inv = exp2f(-(float)j * 0.8304820236903231f);
    g_cos[idx] = cosf(pos * inv);
    g_sin[idx] = sinf(pos * inv);
}

__global__ void rope_apply_kernel() {
    int n = blockIdx.x, t = threadIdx.x;
    int s = n & (SEQ - 1);
    int hh = t >> 5, p = t & 31;
    float c = g_cos[(s << 5) + p], sn = g_sin[(s << 5) + p];
    float* q = g_qkv + (size_t)n * QKVN + hh * HDIM + 2 * p;
    float2 xq = *(float2*)q;
    *(float2*)q = make_float2(xq.x * c - xq.y * sn, xq.y * c + xq.x * sn);
    float* k = q + DMODEL;
    float2 xk = *(float2*)k;
    *(float2*)k = make_float2(xk.x * c - xk.y * sn, xk.y * c + xk.x * sn);
}

// ===========================================================================
// fp32 -> bf16 hi/lo split
// ===========================================================================
__global__ void split_kernel(const float* __restrict__ in,
                             __nv_bfloat16* __restrict__ hi,
                             __nv_bfloat16* __restrict__ lo, int n4) {
    int i = blockIdx.x * blockDim.x + threadIdx.x;
    if (i >= n4) return;
    float4 v = *(const float4*)(in + (size_t)i * 4);
    __nv_bfloat16 h0 = __float2bfloat16(v.x);
    __nv_bfloat16 h1 = __float2bfloat16(v.y);
    __nv_bfloat16 h2 = __float2bfloat16(v.z);
    __nv_bfloat16 h3 = __float2bfloat16(v.w);
    __nv_bfloat162 hp0 = {h0, h1}, hp1 = {h2, h3};
    *(__nv_bfloat162*)(hi + (size_t)i * 4)     = hp0;
    *(__nv_bfloat162*)(hi + (size_t)i * 4 + 2) = hp1;
    __nv_bfloat162 lp0 = {__float2bfloat16(v.x - __bfloat162float(h0)),
                          __float2bfloat16(v.y - __bfloat162float(h1))};
    __nv_bfloat162 lp1 = {__float2bfloat16(v.z - __bfloat162float(h2)),
                          __float2bfloat16(v.w - __bfloat162float(h3))};
    *(__nv_bfloat162*)(lo + (size_t)i * 4)     = lp0;
    *(__nv_bfloat162*)(lo + (size_t)i * 4 + 2) = lp1;
}

// ===========================================================================
// HMMA bf16-split GEMM: C[M,N] = A[M,768] * B[N,768]^T (+bias)
// CTA 128x128, 8 warps (2m x 4n), warp tile 64x32.
// K chunked by 64, 2-stage cp.async pipeline, padded smem rows (72 bf16).
// ===========================================================================
#define CHUNK 64
#define ROWB 144                      // 72 bf16 per smem row
#define TILE_BYTES (128 * ROWB)       // 18432
#define STAGE_BYTES (4 * TILE_BYTES)  // 73728
#define GEMM_SMEM (2 * STAGE_BYTES)   // 147456
#define NCHUNK (KDIM / CHUNK)         // 12

__global__ __launch_bounds__(256, 1)
void gemm_mma(const __nv_bfloat16* __restrict__ Ah, const __nv_bfloat16* __restrict__ Al,
              const __nv_bfloat16* __restrict__ Bh, const __nv_bfloat16* __restrict__ Bl,
              float* __restrict__ C, int N, const float* __restrict__ bias)
{
    extern __shared__ __align__(128) char sm[];
    const int t = threadIdx.x;
    const int wid = t >> 5, lane = t & 31;
    const int wm = wid & 1, wn = wid >> 1;
    const int gid = lane >> 2, tid4 = lane & 3;
    const int bm = blockIdx.y * 128;
    const int bn = blockIdx.x * 128;

    float acc[4][4][4];
#pragma unroll
    for (int i = 0; i < 4; i++)
#pragma unroll
        for (int j = 0; j < 4; j++)
#pragma unroll
            for (int k = 0; k < 4; k++) acc[i][j][k] = 0.0f;

    // per-thread copy slots: 16 segments of 16B
    const int seg_tile = (t * 16) >> 10;          // constant per thread? no — compute per i
    (void)seg_tile;

    auto issue_copy = [&](int c) {
        char* dst0 = sm + (c & 1) * STAGE_BYTES;
        const int k0 = c * CHUNK;
#pragma unroll
        for (int i = 0; i < 16; i++) {
            int idx = t + 256 * i;
            int tile = idx >> 10;
            int rem = idx & 1023;
            int row = rem >> 3, g = rem & 7;
            uint32_t d = smem_u32(dst0 + tile * TILE_BYTES + row * ROWB + g * 16);
            const __nv_bfloat16* s;
            if (tile == 0)      s = Ah + (size_t)(bm + row) * KDIM + k0 + g * 8;
            else if (tile == 1) s = Al + (size_t)(bm + row) * KDIM + k0 + g * 8;
            else if (tile == 2) s = Bh + (size_t)(bn + row) * KDIM + k0 + g * 8;
            else                s = Bl + (size_t)(bn + row) * KDIM + k0 + g * 8;
            CP16(d, s);
        }
        CP_COMMIT();
    };

    issue_copy(0);

    for (int c = 0; c < NCHUNK; c++) {
        if (c + 1 < NCHUNK) {
            issue_copy(c + 1);
            CP_WAIT(1);
        } else {
            CP_WAIT(0);
        }
        __syncthreads();

        char* sb  = sm + (c & 1) * STAGE_BYTES;
        char* As  = sb;
        char* Asl = sb + TILE_BYTES;
        char* Bs  = sb + 2 * TILE_BYTES;
        char* Bsl = sb + 3 * TILE_BYTES;

#pragma unroll
        for (int ks = 0; ks < 4; ks++) {
            const int kb = (ks * 16 + tid4 * 2) * 2;  // byte offset of this thread's k pair
            uint32_t ah[4][4], al[4][4], bh[4][2], bl[4][2];
#pragma unroll
            for (int mi = 0; mi < 4; mi++) {
                int r0 = wm * 64 + mi * 16 + gid;
                const uint32_t* p0 = (const uint32_t*)(As + r0 * ROWB + kb);
                const uint32_t* p1 = (const uint32_t*)(As + (r0 + 8) * ROWB + kb);
                ah[mi][0] = p0[0]; ah[mi][1] = p1[0]; ah[mi][2] = p0[4]; ah[mi][3] = p1[4];
                const uint32_t* q0 = (const uint32_t*)(Asl + r0 * ROWB + kb);
                const uint32_t* q1 = (const uint32_t*)(Asl + (r0 + 8) * ROWB + kb);
                al[mi][0] = q0[0]; al[mi][1] = q1[0]; al[mi][2] = q0[4]; al[mi][3] = q1[4];
            }
#pragma unroll
            for (int ni = 0; ni < 4; ni++) {
                int n0 = wn * 32 + ni * 8 + gid;
                const uint32_t* p = (const uint32_t*)(Bs + n0 * ROWB + kb);
                bh[ni][0] = p[0]; bh[ni][1] = p[4];
                const uint32_t* q = (const uint32_t*)(Bsl + n0 * ROWB + kb);
                bl[ni][0] = q[0]; bl[ni][1] = q[4];
            }
#pragma unroll
            for (int mi = 0; mi < 4; mi++)
#pragma unroll
                for (int ni = 0; ni < 4; ni++) {
                    mma_bf16(acc[mi][ni], ah[mi], bh[ni]);
                    mma_bf16(acc[mi][ni], ah[mi], bl[ni]);
                    mma_bf16(acc[mi][ni], al[mi], bh[ni]);
                }
        }
        __syncthreads();
    }

    // epilogue
#pragma unroll
    for (int mi = 0; mi < 4; mi++) {
        int r0 = bm + wm * 64 + mi * 16 + gid;
#pragma unroll
        for (int ni = 0; ni < 4; ni++) {
            int cc = bn + wn * 32 + ni * 8 + tid4 * 2;
            float2 v0 = make_float2(acc[mi][ni][0], acc[mi][ni][1]);
            float2 v1 = make_float2(acc[mi][ni][2], acc[mi][ni][3]);
            if (bias) {
                float2 bv = *(const float2*)&bias[cc];
                v0.x += bv.x; v0.y += bv.y;
                v1.x += bv.x; v1.y += bv.y;
            }
            *(float2*)&C[(size_t)r0 * N + cc]       = v0;
            *(float2*)&C[(size_t)(r0 + 8) * N + cc] = v1;
        }
    }
}

// ===========================================================================
// Register-tiled SIMT flash attention.
// grid=(16, 192), block=256. Thread (ty,tx) owns 4x4 tiles of S/P and O.
// ===========================================================================
#define ATN_SMEM (4 * 64 * 64 * 4)   // 64KB

__global__ __launch_bounds__(256)
void attn_kernel()
{
    extern __shared__ __align__(16) float asm_[];
    float* Qs = asm_;            // [64][64] (row, d)
    float* Kt = asm_ + 4096;     // [64][64] (d, kv) transposed
    float* Vs = asm_ + 8192;     // [64][64] (kv, col)
    float* Ps = asm_ + 12288;    // [64][64] (row, kv)

    const int bh = blockIdx.y;
    const int bt = bh / NHEADS;
    const int hh = bh % NHEADS;
    const int q0 = blockIdx.x * 64;
    const int t  = threadIdx.x;
    const int ty = t >> 4, tx = t & 15;
    const int wid = t >> 5, lane = t & 31;

    const float* qbase = g_qkv + (size_t)bt * SEQ * QKVN + hh * HDIM;
    const float* kbase = qbase + DMODEL;
    const float* vbase = qbase + 2 * DMODEL;

#pragma unroll
    for (int i = 0; i < 4; i++) {
        int idx = t + 256 * i;
        int row = idx >> 4, c4 = idx & 15;
        float4 v = *(const float4*)&qbase[(size_t)(q0 + row) * QKVN + c4 * 4];
        v.x *= 0.125f; v.y *= 0.125f; v.z *= 0.125f; v.w *= 0.125f;
        *(float4*)&Qs[row * 64 + c4 * 4] = v;
    }

    float m[4], l[4], o[4][4];
#pragma unroll
    for (int i = 0; i < 4; i++) {
        m[i] = -1e30f; l[i] = 0.0f;
#pragma unroll
        for (int j = 0; j < 4; j++) o[i][j] = 0.0f;
    }

    for (int kt = 0; kt < SEQ / 64; kt++) {
        __syncthreads();
        {
            int kv = (wid & 1) * 32 + lane;
            int c0 = (wid >> 1) * 16;
            const float* krow = &kbase[(size_t)(kt * 64 + kv) * QKVN + c0];
#pragma unroll
            for (int j = 0; j < 4; j++) {
                float4 v = *(const float4*)&krow[j * 4];
                Kt[(c0 + j * 4 + 0) * 64 + kv] = v.x;
                Kt[(c0 + j * 4 + 1) * 64 + kv] = v.y;
                Kt[(c0 + j * 4 + 2) * 64 + kv] = v.z;
                Kt[(c0 + j * 4 + 3) * 64 + kv] = v.w;
            }
        }
#pragma unroll
        for (int i = 0; i < 4; i++) {
            int idx = t + 256 * i;
            int row = idx >> 4, c4 = idx & 15;
            *(float4*)&Vs[row * 64 + c4 * 4] =
                *(const float4*)&vbase[(size_t)(kt * 64 + row) * QKVN + c4 * 4];
        }
        __syncthreads();

        float s[4][4];
#pragma unroll
        for (int i = 0; i < 4; i++)
#pragma unroll
            for (int j = 0; j < 4; j++) s[i][j] = 0.0f;

#pragma unroll 4
        for (int d0 = 0; d0 < 64; d0 += 4) {
            float4 a0 = *(const float4*)&Qs[(ty * 4 + 0) * 64 + d0];
            float4 a1 = *(const float4*)&Qs[(ty * 4 + 1) * 64 + d0];
            float4 a2 = *(const float4*)&Qs[(ty * 4 + 2) * 64 + d0];
            float4 a3 = *(const float4*)&Qs[(ty * 4 + 3) * 64 + d0];
#pragma unroll
            for (int dd = 0; dd < 4; dd++) {
                float4 b = *(const float4*)&Kt[(d0 + dd) * 64 + tx * 4];
                float av[4] = { dd == 0 ? a0.x : dd == 1 ? a0.y : dd == 2 ? a0.z : a0.w,
                                dd == 0 ? a1.x : dd == 1 ? a1.y : dd == 2 ? a1.z : a1.w,
                                dd == 0 ? a2.x : dd == 1 ? a2.y : dd == 2 ? a2.z : a2.w,
                                dd == 0 ? a3.x : dd == 1 ? a3.y : dd == 2 ? a3.z : a3.w };
#pragma unroll
                for (int i = 0; i < 4; i++) {
                    s[i][0] = fmaf(av[i], b.x, s[i][0]);
                    s[i][1] = fmaf(av[i], b.y, s[i][1]);
                    s[i][2] = fmaf(av[i], b.z, s[i][2]);
                    s[i][3] = fmaf(av[i], b.w, s[i][3]);
                }
            }
        }

#pragma unroll
        for (int i = 0; i < 4; i++) {
            float mt = fmaxf(fmaxf(s[i][0], s[i][1]), fmaxf(s[i][2], s[i][3]));
            mt = fmaxf(mt, __shfl_xor_sync(0xffffffffu, mt, 1));
            mt = fmaxf(mt, __shfl_xor_sync(0xffffffffu, mt, 2));
            mt = fmaxf(mt, __shfl_xor_sync(0xffffffffu, mt, 4));
            mt = fmaxf(mt, __shfl_xor_sync(0xffffffffu, mt, 8));
            float mnew = fmaxf(m[i], mt);
            float alpha = __expf(m[i] - mnew);
            float ps = 0.0f;
#pragma unroll
            for (int j = 0; j < 4; j++) {
                float p = __expf(s[i][j] - mnew);
                s[i][j] = p;
                ps += p;
            }
            ps += __shfl_xor_sync(0xffffffffu, ps, 1);
            ps += __shfl_xor_sync(0xffffffffu, ps, 2);
            ps += __shfl_xor_sync(0xffffffffu, ps, 4);
            ps += __shfl_xor_sync(0xffffffffu, ps, 8);
            l[i] = l[i] * alpha + ps;
            m[i] = mnew;
#pragma unroll
            for (int j = 0; j < 4; j++) o[i][j] *= alpha;
        }

#pragma unroll
        for (int i = 0; i < 4; i++)
            *(float4*)&Ps[(ty * 4 + i) * 64 + tx * 4] =
                make_float4(s[i][0], s[i][1], s[i][2], s[i][3]);
        __syncthreads();

#pragma unroll 4
        for (int c0 = 0; c0 < 64; c0 += 4) {
            float4 a0 = *(const float4*)&Ps[(ty * 4 + 0) * 64 + c0];
            float4 a1 = *(const float4*)&Ps[(ty * 4 + 1) * 64 + c0];
            float4 a2 = *(const float4*)&Ps[(ty * 4 + 2) * 64 + c0];
            float4 a3 = *(const float4*)&Ps[(ty * 4 + 3) * 64 + c0];
#pragma unroll
            for (int cc = 0; cc < 4; cc++) {
                float4 b = *(const float4*)&Vs[(c0 + cc) * 64 + tx * 4];
                float av[4] = { cc == 0 ? a0.x : cc == 1 ? a0.y : cc == 2 ? a0.z : a0.w,
                                cc == 0 ? a1.x : cc == 1 ? a1.y : cc == 2 ? a1.z : a1.w,
                                cc == 0 ? a2.x : cc == 1 ? a2.y : cc == 2 ? a2.z : a2.w,
                                cc == 0 ? a3.x : cc == 1 ? a3.y : cc == 2 ? a3.z : a3.w };
#pragma unroll
                for (int i = 0; i < 4; i++) {
                    o[i][0] = fmaf(av[i], b.x, o[i][0]);
                    o[i][1] = fmaf(av[i], b.y, o[i][1]);
                    o[i][2] = fmaf(av[i], b.z, o[i][2]);
                    o[i][3] = fmaf(av[i], b.w, o[i][3]);
                }
            }
        }
    }

#pragma unroll
    for (int i = 0; i < 4; i++) {
        float inv = 1.0f / l[i];
        float* orow = g_o + (size_t)(bt * SEQ + q0 + ty * 4 + i) * DMODEL + hh * HDIM + tx * 4;
        *(float4*)orow = make_float4(o[i][0] * inv, o[i][1] * inv, o[i][2] * inv, o[i][3] * inv);
    }
}

// ===========================================================================
extern "C" void kernel_launch(void* const* d_in, const int* in_sizes, int n_in,
                              void* d_out, int out_size)
{
    const float* x     = (const float*)d_in[0];
    const float* w_qkv = (const float*)d_in[1];
    const float* w_out = (const float*)d_in[2];
    const float* b_out = (const float*)d_in[3];
    float* out = (float*)d_out;

    float *qkv, *o;
    __nv_bfloat16 *Ah, *Al, *Bh, *Bl;
    cudaGetSymbolAddress((void**)&qkv, g_qkv);
    cudaGetSymbolAddress((void**)&o, g_o);
    cudaGetSymbolAddress((void**)&Ah, g_Ah);
    cudaGetSymbolAddress((void**)&Al, g_Al);
    cudaGetSymbolAddress((void**)&Bh, g_Bh);
    cudaGetSymbolAddress((void**)&Bl, g_Bl);

    cudaFuncSetAttribute(gemm_mma, cudaFuncAttributeMaxDynamicSharedMemorySize, GEMM_SMEM);
    cudaFuncSetAttribute(attn_kernel, cudaFuncAttributeMaxDynamicSharedMemorySize, ATN_SMEM);

    rope_table_kernel<<<(SEQ * 32 + 255) / 256, 256>>>();

    {
        int n4 = MROWS * KDIM / 4;
        split_kernel<<<(n4 + 255) / 256, 256>>>(x, Ah, Al, n4);
        int n4b = QKVN * KDIM / 4;
        split_kernel<<<(n4b + 255) / 256, 256>>>(w_qkv, Bh, Bl, n4b);
    }

    gemm_mma<<<dim3(QKVN / 128, MROWS / 128), 256, GEMM_SMEM>>>(
        Ah, Al, Bh, Bl, qkv, QKVN, nullptr);

    rope_apply_kernel<<<MROWS, 384>>>();

    attn_kernel<<<dim3(SEQ / 64, BTC * NHEADS), 256, ATN_SMEM>>>();

    {
        int n4 = MROWS * KDIM / 4;
        split_kernel<<<(n4 + 255) / 256, 256>>>(o, Ah, Al, n4);
        int n4b = DMODEL * KDIM / 4;
        split_kernel<<<(n4b + 255) / 256, 256>>>(w_out, Bh, Bl, n4b);
    }
    gemm_mma<<<dim3(DMODEL / 128, MROWS / 128), 256, GEMM_SMEM>>>(
        Ah, Al, Bh, Bl, out, DMODEL, b_out);
}

// round 4
// speedup vs baseline: 8.2426x; 1.6865x over previous
#include <cuda_runtime.h>
#include <cuda_bf16.h>
#include <math.h>
#include <stdint.h>

// Problem constants
#define BTC    16
#define SEQ    1024
#define DMODEL 768
#define NHEADS 12
#define HDIM   64
#define MROWS  (BTC * SEQ)     // 16384
#define QKVN   (3 * DMODEL)    // 2304
#define KDIM   768

// Scratch (static device globals: allocation-guard safe)
__device__ float g_qkv[(size_t)MROWS * QKVN];
__device__ float g_cos[SEQ * 32];
__device__ float g_sin[SEQ * 32];
__device__ __nv_bfloat16 g_Ah[(size_t)MROWS * KDIM];
__device__ __nv_bfloat16 g_Al[(size_t)MROWS * KDIM];
__device__ __nv_bfloat16 g_Bh[(size_t)QKVN * KDIM];
__device__ __nv_bfloat16 g_Bl[(size_t)QKVN * KDIM];

// ===========================================================================
// Helpers
// ===========================================================================
__device__ __forceinline__ uint32_t smem_u32(const void* p) {
    uint32_t a;
    asm("{ .reg .u64 t; cvta.to.shared.u64 t, %1; cvt.u32.u64 %0, t; }" : "=r"(a) : "l"(p));
    return a;
}
#define CP16(dst, src) \
    asm volatile("cp.async.cg.shared.global [%0], [%1], 16;" :: "r"(dst), "l"(src))
#define CP_COMMIT() asm volatile("cp.async.commit_group;")
#define CP_WAIT(n)  asm volatile("cp.async.wait_group %0;" :: "n"(n))

__device__ __forceinline__ void mma_bf16(float* d, const uint32_t* a, const uint32_t* b) {
    asm volatile(
        "mma.sync.aligned.m16n8k16.row.col.f32.bf16.bf16.f32 "
        "{%0,%1,%2,%3}, {%4,%5,%6,%7}, {%8,%9}, {%0,%1,%2,%3};"
        : "+f"(d[0]), "+f"(d[1]), "+f"(d[2]), "+f"(d[3])
        : "r"(a[0]), "r"(a[1]), "r"(a[2]), "r"(a[3]), "r"(b[0]), "r"(b[1]));
}

// pack two floats -> bf16x2 word (lo element in low 16 bits)
__device__ __forceinline__ uint32_t pack_bf16(float lo, float hi) {
    uint32_t d;
    asm("cvt.rn.bf16x2.f32 %0, %1, %2;" : "=r"(d) : "f"(hi), "f"(lo));
    return d;
}
// split (x,y) -> hi word + residual-lo word
__device__ __forceinline__ void split2(float x, float y, uint32_t& h, uint32_t& l) {
    h = pack_bf16(x, y);
    __nv_bfloat162 hv = *reinterpret_cast<__nv_bfloat162*>(&h);
    l = pack_bf16(x - __bfloat162float(hv.x), y - __bfloat162float(hv.y));
}

// ===========================================================================
// RoPE kernels
// ===========================================================================
__global__ void rope_table_kernel() {
    int idx = blockIdx.x * blockDim.x + threadIdx.x;
    if (idx >= SEQ * 32) return;
    int s = idx >> 5, p = idx & 31;
    float pos = (p < 16) ? (float)(s >> 5) : (float)(s & 31);
    int j = p & 15;
    float inv = exp2f(-(float)j * 0.8304820236903231f);
    g_cos[idx] = cosf(pos * inv);
    g_sin[idx] = sinf(pos * inv);
}

__global__ void rope_apply_kernel() {
    int n = blockIdx.x, t = threadIdx.x;
    int s = n & (SEQ - 1);
    int hh = t >> 5, p = t & 31;
    float c = g_cos[(s << 5) + p], sn = g_sin[(s << 5) + p];
    float* q = g_qkv + (size_t)n * QKVN + hh * HDIM + 2 * p;
    float2 xq = *(float2*)q;
    *(float2*)q = make_float2(xq.x * c - xq.y * sn, xq.y * c + xq.x * sn);
    float* k = q + DMODEL;
    float2 xk = *(float2*)k;
    *(float2*)k = make_float2(xk.x * c - xk.y * sn, xk.y * c + xk.x * sn);
}

// ===========================================================================
// fp32 -> bf16 hi/lo split
// ===========================================================================
__global__ void split_kernel(const float* __restrict__ in,
                             __nv_bfloat16* __restrict__ hi,
                             __nv_bfloat16* __restrict__ lo, int n4) {
    int i = blockIdx.x * blockDim.x + threadIdx.x;
    if (i >= n4) return;
    float4 v = *(const float4*)(in + (size_t)i * 4);
    uint32_t h0, l0, h1, l1;
    split2(v.x, v.y, h0, l0);
    split2(v.z, v.w, h1, l1);
    *(uint2*)(hi + (size_t)i * 4) = make_uint2(h0, h1);
    *(uint2*)(lo + (size_t)i * 4) = make_uint2(l0, l1);
}

// ===========================================================================
// HMMA bf16-split GEMM: C[M,N] = A[M,768] * B[N,768]^T (+bias)
// CTA 128x128, 8 warps (2m x 4n), warp tile 64x32.
// ===========================================================================
#define CHUNK 64
#define ROWB 144
#define TILE_BYTES (128 * ROWB)
#define STAGE_BYTES (4 * TILE_BYTES)
#define GEMM_SMEM (2 * STAGE_BYTES)
#define NCHUNK (KDIM / CHUNK)

__global__ __launch_bounds__(256, 1)
void gemm_mma(const __nv_bfloat16* __restrict__ Ah, const __nv_bfloat16* __restrict__ Al,
              const __nv_bfloat16* __restrict__ Bh, const __nv_bfloat16* __restrict__ Bl,
              float* __restrict__ C, int N, const float* __restrict__ bias)
{
    extern __shared__ __align__(128) char sm[];
    const int t = threadIdx.x;
    const int wid = t >> 5, lane = t & 31;
    const int wm = wid & 1, wn = wid >> 1;
    const int gid = lane >> 2, tid4 = lane & 3;
    const int bm = blockIdx.y * 128;
    const int bn = blockIdx.x * 128;

    float acc[4][4][4];
#pragma unroll
    for (int i = 0; i < 4; i++)
#pragma unroll
        for (int j = 0; j < 4; j++)
#pragma unroll
            for (int k = 0; k < 4; k++) acc[i][j][k] = 0.0f;

    auto issue_copy = [&](int c) {
        char* dst0 = sm + (c & 1) * STAGE_BYTES;
        const int k0 = c * CHUNK;
#pragma unroll
        for (int i = 0; i < 16; i++) {
            int idx = t + 256 * i;
            int tile = idx >> 10;
            int rem = idx & 1023;
            int row = rem >> 3, g = rem & 7;
            uint32_t d = smem_u32(dst0 + tile * TILE_BYTES + row * ROWB + g * 16);
            const __nv_bfloat16* s;
            if (tile == 0)      s = Ah + (size_t)(bm + row) * KDIM + k0 + g * 8;
            else if (tile == 1) s = Al + (size_t)(bm + row) * KDIM + k0 + g * 8;
            else if (tile == 2) s = Bh + (size_t)(bn + row) * KDIM + k0 + g * 8;
            else                s = Bl + (size_t)(bn + row) * KDIM + k0 + g * 8;
            CP16(d, s);
        }
        CP_COMMIT();
    };

    issue_copy(0);

    for (int c = 0; c < NCHUNK; c++) {
        if (c + 1 < NCHUNK) {
            issue_copy(c + 1);
            CP_WAIT(1);
        } else {
            CP_WAIT(0);
        }
        __syncthreads();

        char* sb  = sm + (c & 1) * STAGE_BYTES;
        char* As  = sb;
        char* Asl = sb + TILE_BYTES;
        char* Bs  = sb + 2 * TILE_BYTES;
        char* Bsl = sb + 3 * TILE_BYTES;

#pragma unroll
        for (int ks = 0; ks < 4; ks++) {
            const int kb = (ks * 16 + tid4 * 2) * 2;
            uint32_t ah[4][4], al[4][4], bh[4][2], bl[4][2];
#pragma unroll
            for (int mi = 0; mi < 4; mi++) {
                int r0 = wm * 64 + mi * 16 + gid;
                const uint32_t* p0 = (const uint32_t*)(As + r0 * ROWB + kb);
                const uint32_t* p1 = (const uint32_t*)(As + (r0 + 8) * ROWB + kb);
                ah[mi][0] = p0[0]; ah[mi][1] = p1[0]; ah[mi][2] = p0[4]; ah[mi][3] = p1[4];
                const uint32_t* q0 = (const uint32_t*)(Asl + r0 * ROWB + kb);
                const uint32_t* q1 = (const uint32_t*)(Asl + (r0 + 8) * ROWB + kb);
                al[mi][0] = q0[0]; al[mi][1] = q1[0]; al[mi][2] = q0[4]; al[mi][3] = q1[4];
            }
#pragma unroll
            for (int ni = 0; ni < 4; ni++) {
                int n0 = wn * 32 + ni * 8 + gid;
                const uint32_t* p = (const uint32_t*)(Bs + n0 * ROWB + kb);
                bh[ni][0] = p[0]; bh[ni][1] = p[4];
                const uint32_t* q = (const uint32_t*)(Bsl + n0 * ROWB + kb);
                bl[ni][0] = q[0]; bl[ni][1] = q[4];
            }
#pragma unroll
            for (int mi = 0; mi < 4; mi++)
#pragma unroll
                for (int ni = 0; ni < 4; ni++) {
                    mma_bf16(acc[mi][ni], ah[mi], bh[ni]);
                    mma_bf16(acc[mi][ni], ah[mi], bl[ni]);
                    mma_bf16(acc[mi][ni], al[mi], bh[ni]);
                }
        }
        __syncthreads();
    }

#pragma unroll
    for (int mi = 0; mi < 4; mi++) {
        int r0 = bm + wm * 64 + mi * 16 + gid;
#pragma unroll
        for (int ni = 0; ni < 4; ni++) {
            int cc = bn + wn * 32 + ni * 8 + tid4 * 2;
            float2 v0 = make_float2(acc[mi][ni][0], acc[mi][ni][1]);
            float2 v1 = make_float2(acc[mi][ni][2], acc[mi][ni][3]);
            if (bias) {
                float2 bv = *(const float2*)&bias[cc];
                v0.x += bv.x; v0.y += bv.y;
                v1.x += bv.x; v1.y += bv.y;
            }
            *(float2*)&C[(size_t)r0 * N + cc]       = v0;
            *(float2*)&C[(size_t)(r0 + 8) * N + cc] = v1;
        }
    }
}

// ===========================================================================
// HMMA flash attention.
// grid=(8, 192), block=256 (8 warps). CTA: 128 q-rows; kv tiles of 64.
// Warp w: q rows w*16..w*16+15. S via 3-term bf16-split MMA, online softmax
// in C-fragments, P re-split to bf16 in registers (C frag == A frag layout),
// PV via 3-term MMA with V transposed in smem. Epilogue writes bf16 hi/lo
// directly into the out-projection A buffers.
// Smem rows padded to 144B -> all compute LDS conflict-free.
// ===========================================================================
#define AP 144
#define SQH 0
#define SQL (SQH + 128 * AP)          // 18432
#define SKH (SQL + 128 * AP)          // 36864
#define SKL (SKH + 64 * AP)           // 46080
#define SVH (SKL + 64 * AP)           // 55296
#define SVL (SVH + 64 * AP)           // 64512
#define ATN_SMEM (SVL + 64 * AP)      // 73728

__global__ __launch_bounds__(256)
void attn_mma(__nv_bfloat16* __restrict__ Oh, __nv_bfloat16* __restrict__ Ol)
{
    extern __shared__ __align__(16) char sm[];
    const int bh = blockIdx.y;
    const int bt = bh / NHEADS;
    const int hh = bh % NHEADS;
    const int q0 = blockIdx.x * 128;
    const int t = threadIdx.x;
    const int wid = t >> 5, lane = t & 31;
    const int gid = lane >> 2, tid4 = lane & 3;

    const float* qg = g_qkv + (size_t)(bt * SEQ + q0) * QKVN + hh * HDIM;

    // ---- load Q (once), scale 1/8, split hi/lo ----
#pragma unroll
    for (int i = 0; i < 8; i++) {
        int w = t + 256 * i;               // 2048 items = 128 rows x 16 dgroups
        int dg = w & 15, row = w >> 4;
        float4 v = *(const float4*)(qg + (size_t)row * QKVN + dg * 4);
        v.x *= 0.125f; v.y *= 0.125f; v.z *= 0.125f; v.w *= 0.125f;
        uint32_t h0, l0, h1, l1;
        split2(v.x, v.y, h0, l0);
        split2(v.z, v.w, h1, l1);
        *(uint2*)(sm + SQH + row * AP + dg * 8) = make_uint2(h0, h1);
        *(uint2*)(sm + SQL + row * AP + dg * 8) = make_uint2(l0, l1);
    }

    float m0 = -1e30f, m1 = -1e30f, l0s = 0.0f, l1s = 0.0f;
    float o[8][4];
#pragma unroll
    for (int j = 0; j < 8; j++)
#pragma unroll
        for (int k = 0; k < 4; k++) o[j][k] = 0.0f;

    const int qrb = wid * 16 + gid;

    for (int kt = 0; kt < SEQ / 64; kt++) {
        __syncthreads();
        // ---- load K tile (natural kv,d) split hi/lo ----
        const float* kg = g_qkv + (size_t)(bt * SEQ + kt * 64) * QKVN + DMODEL + hh * HDIM;
#pragma unroll
        for (int i = 0; i < 4; i++) {
            int w = t + 256 * i;           // 1024 items = 64 kv x 16 dgroups
            int dg = w & 15, kv = w >> 4;
            float4 v = *(const float4*)(kg + (size_t)kv * QKVN + dg * 4);
            uint32_t h0, l0, h1, l1;
            split2(v.x, v.y, h0, l0);
            split2(v.z, v.w, h1, l1);
            *(uint2*)(sm + SKH + kv * AP + dg * 8) = make_uint2(h0, h1);
            *(uint2*)(sm + SKL + kv * AP + dg * 8) = make_uint2(l0, l1);
        }
        // ---- load V tile transposed (col, kv) split hi/lo ----
        const float* vg = g_qkv + (size_t)(bt * SEQ + kt * 64) * QKVN + 2 * DMODEL + hh * HDIM;
#pragma unroll
        for (int i = 0; i < 2; i++) {
            int w = t + 256 * i;           // 512 items = 32 kv-pairs x 16 cgroups
            int kvp = w & 31, cg = w >> 5;
            int kv0 = kvp * 2;
            float4 va = *(const float4*)(vg + (size_t)kv0 * QKVN + cg * 4);
            float4 vb = *(const float4*)(vg + (size_t)(kv0 + 1) * QKVN + cg * 4);
            const float ax[4] = {va.x, va.y, va.z, va.w};
            const float bx[4] = {vb.x, vb.y, vb.z, vb.w};
#pragma unroll
            for (int jj = 0; jj < 4; jj++) {
                uint32_t h, l;
                split2(ax[jj], bx[jj], h, l);
                *(uint32_t*)(sm + SVH + (cg * 4 + jj) * AP + kv0 * 2) = h;
                *(uint32_t*)(sm + SVL + (cg * 4 + jj) * AP + kv0 * 2) = l;
            }
        }
        __syncthreads();

        // ---- S = Q K^T (3-term split) ----
        float s[8][4];
#pragma unroll
        for (int j = 0; j < 8; j++)
#pragma unroll
            for (int k = 0; k < 4; k++) s[j][k] = 0.0f;

#pragma unroll
        for (int ks = 0; ks < 4; ks++) {
            const int qo = qrb * AP + ks * 32 + tid4 * 4;
            uint32_t ah[4], al[4];
            ah[0] = *(const uint32_t*)(sm + SQH + qo);
            ah[1] = *(const uint32_t*)(sm + SQH + qo + 8 * AP);
            ah[2] = *(const uint32_t*)(sm + SQH + qo + 16);
            ah[3] = *(const uint32_t*)(sm + SQH + qo + 8 * AP + 16);
            al[0] = *(const uint32_t*)(sm + SQL + qo);
            al[1] = *(const uint32_t*)(sm + SQL + qo + 8 * AP);
            al[2] = *(const uint32_t*)(sm + SQL + qo + 16);
            al[3] = *(const uint32_t*)(sm + SQL + qo + 8 * AP + 16);
#pragma unroll
            for (int j = 0; j < 8; j++) {
                const int ko = (j * 8 + gid) * AP + ks * 32 + tid4 * 4;
                uint32_t kb[2], kl[2];
                kb[0] = *(const uint32_t*)(sm + SKH + ko);
                kb[1] = *(const uint32_t*)(sm + SKH + ko + 16);
                kl[0] = *(const uint32_t*)(sm + SKL + ko);
                kl[1] = *(const uint32_t*)(sm + SKL + ko + 16);
                mma_bf16(s[j], ah, kb);
                mma_bf16(s[j], ah, kl);
                mma_bf16(s[j], al, kb);
            }
        }

        // ---- online softmax (rows gid / gid+8; reduce over tid4 lanes) ----
        float mt0 = -1e30f, mt1 = -1e30f;
#pragma unroll
        for (int j = 0; j < 8; j++) {
            mt0 = fmaxf(mt0, fmaxf(s[j][0], s[j][1]));
            mt1 = fmaxf(mt1, fmaxf(s[j][2], s[j][3]));
        }
        mt0 = fmaxf(mt0, __shfl_xor_sync(0xffffffffu, mt0, 1));
        mt0 = fmaxf(mt0, __shfl_xor_sync(0xffffffffu, mt0, 2));
        mt1 = fmaxf(mt1, __shfl_xor_sync(0xffffffffu, mt1, 1));
        mt1 = fmaxf(mt1, __shfl_xor_sync(0xffffffffu, mt1, 2));
        float mn0 = fmaxf(m0, mt0), mn1 = fmaxf(m1, mt1);
        float a0 = __expf(m0 - mn0), a1 = __expf(m1 - mn1);
        m0 = mn0; m1 = mn1;
        float ps0 = 0.0f, ps1 = 0.0f;
#pragma unroll
        for (int j = 0; j < 8; j++) {
            s[j][0] = __expf(s[j][0] - m0);
            s[j][1] = __expf(s[j][1] - m0);
            s[j][2] = __expf(s[j][2] - m1);
            s[j][3] = __expf(s[j][3] - m1);
            ps0 += s[j][0] + s[j][1];
            ps1 += s[j][2] + s[j][3];
        }
        ps0 += __shfl_xor_sync(0xffffffffu, ps0, 1);
        ps0 += __shfl_xor_sync(0xffffffffu, ps0, 2);
        ps1 += __shfl_xor_sync(0xffffffffu, ps1, 1);
        ps1 += __shfl_xor_sync(0xffffffffu, ps1, 2);
        l0s = l0s * a0 + ps0;
        l1s = l1s * a1 + ps1;
#pragma unroll
        for (int j = 0; j < 8; j++) {
            o[j][0] *= a0; o[j][1] *= a0;
            o[j][2] *= a1; o[j][3] *= a1;
        }

        // ---- O += P V (3-term split; P fragments built from S fragments) ----
#pragma unroll
        for (int ks = 0; ks < 4; ks++) {
            uint32_t ph[4], pl[4];
            split2(s[2 * ks][0],     s[2 * ks][1],     ph[0], pl[0]);
            split2(s[2 * ks][2],     s[2 * ks][3],     ph[1], pl[1]);
            split2(s[2 * ks + 1][0], s[2 * ks + 1][1], ph[2], pl[2]);
            split2(s[2 * ks + 1][2], s[2 * ks + 1][3], ph[3], pl[3]);
#pragma unroll
            for (int j = 0; j < 8; j++) {
                const int vo = (j * 8 + gid) * AP + ks * 32 + tid4 * 4;
                uint32_t vh[2], vl[2];
                vh[0] = *(const uint32_t*)(sm + SVH + vo);
                vh[1] = *(const uint32_t*)(sm + SVH + vo + 16);
                vl[0] = *(const uint32_t*)(sm + SVL + vo);
                vl[1] = *(const uint32_t*)(sm + SVL + vo + 16);
                mma_bf16(o[j], ph, vh);
                mma_bf16(o[j], ph, vl);
                mma_bf16(o[j], pl, vh);
            }
        }
    }

    // ---- epilogue: normalize and write bf16 hi/lo directly ----
    const float i0 = 1.0f / l0s, i1 = 1.0f / l1s;
    const size_t r0 = (size_t)(bt * SEQ + q0 + wid * 16 + gid);
#pragma unroll
    for (int j = 0; j < 8; j++) {
        int col = hh * HDIM + j * 8 + tid4 * 2;
        uint32_t h, l;
        split2(o[j][0] * i0, o[j][1] * i0, h, l);
        *(uint32_t*)&Oh[r0 * DMODEL + col] = h;
        *(uint32_t*)&Ol[r0 * DMODEL + col] = l;
        split2(o[j][2] * i1, o[j][3] * i1, h, l);
        *(uint32_t*)&Oh[(r0 + 8) * DMODEL + col] = h;
        *(uint32_t*)&Ol[(r0 + 8) * DMODEL + col] = l;
    }
}

// ===========================================================================
extern "C" void kernel_launch(void* const* d_in, const int* in_sizes, int n_in,
                              void* d_out, int out_size)
{
    const float* x     = (const float*)d_in[0];
    const float* w_qkv = (const float*)d_in[1];
    const float* w_out = (const float*)d_in[2];
    const float* b_out = (const float*)d_in[3];
    float* out = (float*)d_out;

    float* qkv;
    __nv_bfloat16 *Ah, *Al, *Bh, *Bl;
    cudaGetSymbolAddress((void**)&qkv, g_qkv);
    cudaGetSymbolAddress((void**)&Ah, g_Ah);
    cudaGetSymbolAddress((void**)&Al, g_Al);
    cudaGetSymbolAddress((void**)&Bh, g_Bh);
    cudaGetSymbolAddress((void**)&Bl, g_Bl);

    cudaFuncSetAttribute(gemm_mma, cudaFuncAttributeMaxDynamicSharedMemorySize, GEMM_SMEM);
    cudaFuncSetAttribute(attn_mma, cudaFuncAttributeMaxDynamicSharedMemorySize, ATN_SMEM);

    rope_table_kernel<<<(SEQ * 32 + 255) / 256, 256>>>();

    {
        int n4 = MROWS * KDIM / 4;
        split_kernel<<<(n4 + 255) / 256, 256>>>(x, Ah, Al, n4);
        int n4b = QKVN * KDIM / 4;
        split_kernel<<<(n4b + 255) / 256, 256>>>(w_qkv, Bh, Bl, n4b);
    }

    gemm_mma<<<dim3(QKVN / 128, MROWS / 128), 256, GEMM_SMEM>>>(
        Ah, Al, Bh, Bl, qkv, QKVN, nullptr);

    rope_apply_kernel<<<MROWS, 384>>>();

    // attention writes its output straight into the next GEMM's A buffers
    attn_mma<<<dim3(SEQ / 128, BTC * NHEADS), 256, ATN_SMEM>>>(Ah, Al);

    {
        int n4b = DMODEL * KDIM / 4;
        split_kernel<<<(n4b + 255) / 256, 256>>>(w_out, Bh, Bl, n4b);
    }
    gemm_mma<<<dim3(DMODEL / 128, MROWS / 128), 256, GEMM_SMEM>>>(
        Ah, Al, Bh, Bl, out, DMODEL, b_out);
}

// round 5
// speedup vs baseline: 8.6970x; 1.0551x over previous
#include <cuda_runtime.h>
#include <cuda_bf16.h>
#include <math.h>
#include <stdint.h>

// Problem constants
#define BTC    16
#define SEQ    1024
#define DMODEL 768
#define NHEADS 12
#define HDIM   64
#define MROWS  (BTC * SEQ)     // 16384
#define QKVN   (3 * DMODEL)    // 2304
#define KDIM   768

// Scratch (static device globals: allocation-guard safe)
__device__ float g_qkv[(size_t)MROWS * QKVN];
__device__ float g_cos[SEQ * 32];
__device__ float g_sin[SEQ * 32];
__device__ __nv_bfloat16 g_Ah[(size_t)MROWS * KDIM];
__device__ __nv_bfloat16 g_Al[(size_t)MROWS * KDIM];
__device__ __nv_bfloat16 g_Bh[(size_t)QKVN * KDIM];
__device__ __nv_bfloat16 g_Bl[(size_t)QKVN * KDIM];

// ===========================================================================
// Helpers
// ===========================================================================
__device__ __forceinline__ uint32_t smem_u32(const void* p) {
    uint32_t a;
    asm("{ .reg .u64 t; cvta.to.shared.u64 t, %1; cvt.u32.u64 %0, t; }" : "=r"(a) : "l"(p));
    return a;
}
#define CP16(dst, src) \
    asm volatile("cp.async.cg.shared.global [%0], [%1], 16;" :: "r"(dst), "l"(src))
#define CP_COMMIT() asm volatile("cp.async.commit_group;")
#define CP_WAIT(n)  asm volatile("cp.async.wait_group %0;" :: "n"(n))

#define LDSM4(r, a)                                                             \
    asm volatile("ldmatrix.sync.aligned.m8n8.x4.shared.b16 {%0,%1,%2,%3}, [%4];" \
        : "=r"((r)[0]), "=r"((r)[1]), "=r"((r)[2]), "=r"((r)[3]) : "r"(a))

__device__ __forceinline__ void mma_bf16(float* d, const uint32_t* a, const uint32_t* b) {
    asm volatile(
        "mma.sync.aligned.m16n8k16.row.col.f32.bf16.bf16.f32 "
        "{%0,%1,%2,%3}, {%4,%5,%6,%7}, {%8,%9}, {%0,%1,%2,%3};"
        : "+f"(d[0]), "+f"(d[1]), "+f"(d[2]), "+f"(d[3])
        : "r"(a[0]), "r"(a[1]), "r"(a[2]), "r"(a[3]), "r"(b[0]), "r"(b[1]));
}

// pack two floats -> bf16x2 word (lo element in low 16 bits)
__device__ __forceinline__ uint32_t pack_bf16(float lo, float hi) {
    uint32_t d;
    asm("cvt.rn.bf16x2.f32 %0, %1, %2;" : "=r"(d) : "f"(hi), "f"(lo));
    return d;
}
// split (x,y) -> hi word + residual-lo word
__device__ __forceinline__ void split2(float x, float y, uint32_t& h, uint32_t& l) {
    h = pack_bf16(x, y);
    __nv_bfloat162 hv = *reinterpret_cast<__nv_bfloat162*>(&h);
    l = pack_bf16(x - __bfloat162float(hv.x), y - __bfloat162float(hv.y));
}

// ===========================================================================
// RoPE kernels
// ===========================================================================
__global__ void rope_table_kernel() {
    int idx = blockIdx.x * blockDim.x + threadIdx.x;
    if (idx >= SEQ * 32) return;
    int s = idx >> 5, p = idx & 31;
    float pos = (p < 16) ? (float)(s >> 5) : (float)(s & 31);
    int j = p & 15;
    float inv = exp2f(-(float)j * 0.8304820236903231f);
    g_cos[idx] = cosf(pos * inv);
    g_sin[idx] = sinf(pos * inv);
}

__global__ void rope_apply_kernel() {
    int n = blockIdx.x, t = threadIdx.x;
    int s = n & (SEQ - 1);
    int hh = t >> 5, p = t & 31;
    float c = g_cos[(s << 5) + p], sn = g_sin[(s << 5) + p];
    float* q = g_qkv + (size_t)n * QKVN + hh * HDIM + 2 * p;
    float2 xq = *(float2*)q;
    *(float2*)q = make_float2(xq.x * c - xq.y * sn, xq.y * c + xq.x * sn);
    float* k = q + DMODEL;
    float2 xk = *(float2*)k;
    *(float2*)k = make_float2(xk.x * c - xk.y * sn, xk.y * c + xk.x * sn);
}

// ===========================================================================
// fp32 -> bf16 hi/lo split
// ===========================================================================
__global__ void split_kernel(const float* __restrict__ in,
                             __nv_bfloat16* __restrict__ hi,
                             __nv_bfloat16* __restrict__ lo, int n4) {
    int i = blockIdx.x * blockDim.x + threadIdx.x;
    if (i >= n4) return;
    float4 v = *(const float4*)(in + (size_t)i * 4);
    uint32_t h0, l0, h1, l1;
    split2(v.x, v.y, h0, l0);
    split2(v.z, v.w, h1, l1);
    *(uint2*)(hi + (size_t)i * 4) = make_uint2(h0, h1);
    *(uint2*)(lo + (size_t)i * 4) = make_uint2(l0, l1);
}

// ===========================================================================
// HMMA bf16-split GEMM: C[M,N] = A[M,768] * B[N,768]^T (+bias)
// CTA tile 128(M) x 256(N), 8 warps (2m x 4n), warp tile 64x64.
// K chunked by 64, 2-stage cp.async pipeline, ldmatrix fragment loads.
// Rows padded to 144B -> conflict-free LDSM phases (stride 144 % 128 = 16).
// ===========================================================================
#define CHUNK 64
#define ROWB 144
#define A_TILE (128 * ROWB)            // 18432
#define B_TILE (256 * ROWB)            // 36864
#define STAGE_BYTES (2 * A_TILE + 2 * B_TILE)   // 110592
#define OFF_AH 0
#define OFF_AL A_TILE
#define OFF_BH (2 * A_TILE)
#define OFF_BL (2 * A_TILE + B_TILE)
#define GEMM_SMEM (2 * STAGE_BYTES)    // 221184
#define NCHUNK (KDIM / CHUNK)          // 12

__global__ __launch_bounds__(256, 1)
void gemm_mma(const __nv_bfloat16* __restrict__ Ah, const __nv_bfloat16* __restrict__ Al,
              const __nv_bfloat16* __restrict__ Bh, const __nv_bfloat16* __restrict__ Bl,
              float* __restrict__ C, int N, const float* __restrict__ bias)
{
    extern __shared__ __align__(128) char sm[];
    const int t = threadIdx.x;
    const int wid = t >> 5, lane = t & 31;
    const int wm = wid & 1, wn = wid >> 1;
    const int gid = lane >> 2, tid4 = lane & 3;
    const int bm = blockIdx.y * 128;
    const int bn = blockIdx.x * 256;

    float acc[4][8][4];
#pragma unroll
    for (int i = 0; i < 4; i++)
#pragma unroll
        for (int j = 0; j < 8; j++)
#pragma unroll
            for (int k = 0; k < 4; k++) acc[i][j][k] = 0.0f;

    const uint32_t smb = smem_u32(sm);
    // lane-invariant ldmatrix address parts
    const uint32_t aoff = (uint32_t)((wm * 64 + (lane & 15)) * ROWB + ((lane >> 4) & 1) * 16);
    const uint32_t boff = (uint32_t)((wn * 64 + (lane & 7) + ((lane >> 4) & 1) * 8) * ROWB +
                                     ((lane >> 3) & 1) * 16);

    auto issue_copy = [&](int c) {
        char* dst0 = sm + (c & 1) * STAGE_BYTES;
        const int k0 = c * CHUNK;
#pragma unroll
        for (int i = 0; i < 24; i++) {
            int idx = i * 256 + t;             // 6144 segments of 16B
            uint32_t d;
            const __nv_bfloat16* s;
            if (idx < 2048) {                   // A hi | lo
                int row = (idx & 1023) >> 3, g = idx & 7;
                d = smem_u32(dst0 + (idx < 1024 ? OFF_AH : OFF_AL) + row * ROWB + g * 16);
                s = (idx < 1024 ? Ah : Al) + (size_t)(bm + row) * KDIM + k0 + g * 8;
            } else {                            // B hi | lo
                int j = idx - 2048;
                int row = (j & 2047) >> 3, g = j & 7;
                d = smem_u32(dst0 + (j < 2048 ? OFF_BH : OFF_BL) + row * ROWB + g * 16);
                s = (j < 2048 ? Bh : Bl) + (size_t)(bn + row) * KDIM + k0 + g * 8;
            }
            CP16(d, s);
        }
        CP_COMMIT();
    };

    issue_copy(0);

    for (int c = 0; c < NCHUNK; c++) {
        if (c + 1 < NCHUNK) {
            issue_copy(c + 1);
            CP_WAIT(1);
        } else {
            CP_WAIT(0);
        }
        __syncthreads();

        const uint32_t sb = smb + (c & 1) * STAGE_BYTES;

#pragma unroll
        for (int ks = 0; ks < 4; ks++) {
            uint32_t ah[4][4], al[4][4];
#pragma unroll
            for (int mi = 0; mi < 4; mi++) {
                uint32_t a = sb + aoff + mi * (16 * ROWB) + ks * 32;
                LDSM4(ah[mi], a + OFF_AH);
                LDSM4(al[mi], a + OFF_AL);
            }
#pragma unroll
            for (int h = 0; h < 2; h++) {
                uint32_t t0[4], t1[4], u0[4], u1[4];
                uint32_t b0 = sb + boff + (h * 32) * ROWB + ks * 32;
                uint32_t b1 = b0 + 16 * ROWB;
                LDSM4(t0, b0 + OFF_BH);
                LDSM4(t1, b1 + OFF_BH);
                LDSM4(u0, b0 + OFF_BL);
                LDSM4(u1, b1 + OFF_BL);
                uint32_t bh[4][2] = {{t0[0], t0[1]}, {t0[2], t0[3]},
                                     {t1[0], t1[1]}, {t1[2], t1[3]}};
                uint32_t bl[4][2] = {{u0[0], u0[1]}, {u0[2], u0[3]},
                                     {u1[0], u1[1]}, {u1[2], u1[3]}};
#pragma unroll
                for (int mi = 0; mi < 4; mi++)
#pragma unroll
                    for (int ni = 0; ni < 4; ni++) {
                        float* d = acc[mi][h * 4 + ni];
                        mma_bf16(d, ah[mi], bh[ni]);
                        mma_bf16(d, ah[mi], bl[ni]);
                        mma_bf16(d, al[mi], bh[ni]);
                    }
            }
        }
        __syncthreads();
    }

    // epilogue
#pragma unroll
    for (int mi = 0; mi < 4; mi++) {
        int r0 = bm + wm * 64 + mi * 16 + gid;
#pragma unroll
        for (int ni = 0; ni < 8; ni++) {
            int cc = bn + wn * 64 + ni * 8 + tid4 * 2;
            float2 v0 = make_float2(acc[mi][ni][0], acc[mi][ni][1]);
            float2 v1 = make_float2(acc[mi][ni][2], acc[mi][ni][3]);
            if (bias) {
                float2 bv = *(const float2*)&bias[cc];
                v0.x += bv.x; v0.y += bv.y;
                v1.x += bv.x; v1.y += bv.y;
            }
            *(float2*)&C[(size_t)r0 * N + cc]       = v0;
            *(float2*)&C[(size_t)(r0 + 8) * N + cc] = v1;
        }
    }
}

// ===========================================================================
// HMMA flash attention (unchanged from round 4).
// grid=(8, 192), block=256 (8 warps). CTA: 128 q-rows; kv tiles of 64.
// ===========================================================================
#define AP 144
#define SQH 0
#define SQL (SQH + 128 * AP)
#define SKH (SQL + 128 * AP)
#define SKL (SKH + 64 * AP)
#define SVH (SKL + 64 * AP)
#define SVL (SVH + 64 * AP)
#define ATN_SMEM (SVL + 64 * AP)      // 73728

__global__ __launch_bounds__(256)
void attn_mma(__nv_bfloat16* __restrict__ Oh, __nv_bfloat16* __restrict__ Ol)
{
    extern __shared__ __align__(16) char sm[];
    const int bh = blockIdx.y;
    const int bt = bh / NHEADS;
    const int hh = bh % NHEADS;
    const int q0 = blockIdx.x * 128;
    const int t = threadIdx.x;
    const int wid = t >> 5, lane = t & 31;
    const int gid = lane >> 2, tid4 = lane & 3;

    const float* qg = g_qkv + (size_t)(bt * SEQ + q0) * QKVN + hh * HDIM;

#pragma unroll
    for (int i = 0; i < 8; i++) {
        int w = t + 256 * i;
        int dg = w & 15, row = w >> 4;
        float4 v = *(const float4*)(qg + (size_t)row * QKVN + dg * 4);
        v.x *= 0.125f; v.y *= 0.125f; v.z *= 0.125f; v.w *= 0.125f;
        uint32_t h0, l0, h1, l1;
        split2(v.x, v.y, h0, l0);
        split2(v.z, v.w, h1, l1);
        *(uint2*)(sm + SQH + row * AP + dg * 8) = make_uint2(h0, h1);
        *(uint2*)(sm + SQL + row * AP + dg * 8) = make_uint2(l0, l1);
    }

    float m0 = -1e30f, m1 = -1e30f, l0s = 0.0f, l1s = 0.0f;
    float o[8][4];
#pragma unroll
    for (int j = 0; j < 8; j++)
#pragma unroll
        for (int k = 0; k < 4; k++) o[j][k] = 0.0f;

    const int qrb = wid * 16 + gid;

    for (int kt = 0; kt < SEQ / 64; kt++) {
        __syncthreads();
        const float* kg = g_qkv + (size_t)(bt * SEQ + kt * 64) * QKVN + DMODEL + hh * HDIM;
#pragma unroll
        for (int i = 0; i < 4; i++) {
            int w = t + 256 * i;
            int dg = w & 15, kv = w >> 4;
            float4 v = *(const float4*)(kg + (size_t)kv * QKVN + dg * 4);
            uint32_t h0, l0, h1, l1;
            split2(v.x, v.y, h0, l0);
            split2(v.z, v.w, h1, l1);
            *(uint2*)(sm + SKH + kv * AP + dg * 8) = make_uint2(h0, h1);
            *(uint2*)(sm + SKL + kv * AP + dg * 8) = make_uint2(l0, l1);
        }
        const float* vg = g_qkv + (size_t)(bt * SEQ + kt * 64) * QKVN + 2 * DMODEL + hh * HDIM;
#pragma unroll
        for (int i = 0; i < 2; i++) {
            int w = t + 256 * i;
            int kvp = w & 31, cg = w >> 5;
            int kv0 = kvp * 2;
            float4 va = *(const float4*)(vg + (size_t)kv0 * QKVN + cg * 4);
            float4 vb = *(const float4*)(vg + (size_t)(kv0 + 1) * QKVN + cg * 4);
            const float ax[4] = {va.x, va.y, va.z, va.w};
            const float bx[4] = {vb.x, vb.y, vb.z, vb.w};
#pragma unroll
            for (int jj = 0; jj < 4; jj++) {
                uint32_t h, l;
                split2(ax[jj], bx[jj], h, l);
                *(uint32_t*)(sm + SVH + (cg * 4 + jj) * AP + kv0 * 2) = h;
                *(uint32_t*)(sm + SVL + (cg * 4 + jj) * AP + kv0 * 2) = l;
            }
        }
        __syncthreads();

        float s[8][4];
#pragma unroll
        for (int j = 0; j < 8; j++)
#pragma unroll
            for (int k = 0; k < 4; k++) s[j][k] = 0.0f;

#pragma unroll
        for (int ks = 0; ks < 4; ks++) {
            const int qo = qrb * AP + ks * 32 + tid4 * 4;
            uint32_t ah[4], al[4];
            ah[0] = *(const uint32_t*)(sm + SQH + qo);
            ah[1] = *(const uint32_t*)(sm + SQH + qo + 8 * AP);
            ah[2] = *(const uint32_t*)(sm + SQH + qo + 16);
            ah[3] = *(const uint32_t*)(sm + SQH + qo + 8 * AP + 16);
            al[0] = *(const uint32_t*)(sm + SQL + qo);
            al[1] = *(const uint32_t*)(sm + SQL + qo + 8 * AP);
            al[2] = *(const uint32_t*)(sm + SQL + qo + 16);
            al[3] = *(const uint32_t*)(sm + SQL + qo + 8 * AP + 16);
#pragma unroll
            for (int j = 0; j < 8; j++) {
                const int ko = (j * 8 + gid) * AP + ks * 32 + tid4 * 4;
                uint32_t kb[2], kl[2];
                kb[0] = *(const uint32_t*)(sm + SKH + ko);
                kb[1] = *(const uint32_t*)(sm + SKH + ko + 16);
                kl[0] = *(const uint32_t*)(sm + SKL + ko);
                kl[1] = *(const uint32_t*)(sm + SKL + ko + 16);
                mma_bf16(s[j], ah, kb);
                mma_bf16(s[j], ah, kl);
                mma_bf16(s[j], al, kb);
            }
        }

        float mt0 = -1e30f, mt1 = -1e30f;
#pragma unroll
        for (int j = 0; j < 8; j++) {
            mt0 = fmaxf(mt0, fmaxf(s[j][0], s[j][1]));
            mt1 = fmaxf(mt1, fmaxf(s[j][2], s[j][3]));
        }
        mt0 = fmaxf(mt0, __shfl_xor_sync(0xffffffffu, mt0, 1));
        mt0 = fmaxf(mt0, __shfl_xor_sync(0xffffffffu, mt0, 2));
        mt1 = fmaxf(mt1, __shfl_xor_sync(0xffffffffu, mt1, 1));
        mt1 = fmaxf(mt1, __shfl_xor_sync(0xffffffffu, mt1, 2));
        float mn0 = fmaxf(m0, mt0), mn1 = fmaxf(m1, mt1);
        float a0 = __expf(m0 - mn0), a1 = __expf(m1 - mn1);
        m0 = mn0; m1 = mn1;
        float ps0 = 0.0f, ps1 = 0.0f;
#pragma unroll
        for (int j = 0; j < 8; j++) {
            s[j][0] = __expf(s[j][0] - m0);
            s[j][1] = __expf(s[j][1] - m0);
            s[j][2] = __expf(s[j][2] - m1);
            s[j][3] = __expf(s[j][3] - m1);
            ps0 += s[j][0] + s[j][1];
            ps1 += s[j][2] + s[j][3];
        }
        ps0 += __shfl_xor_sync(0xffffffffu, ps0, 1);
        ps0 += __shfl_xor_sync(0xffffffffu, ps0, 2);
        ps1 += __shfl_xor_sync(0xffffffffu, ps1, 1);
        ps1 += __shfl_xor_sync(0xffffffffu, ps1, 2);
        l0s = l0s * a0 + ps0;
        l1s = l1s * a1 + ps1;
#pragma unroll
        for (int j = 0; j < 8; j++) {
            o[j][0] *= a0; o[j][1] *= a0;
            o[j][2] *= a1; o[j][3] *= a1;
        }

#pragma unroll
        for (int ks = 0; ks < 4; ks++) {
            uint32_t ph[4], pl[4];
            split2(s[2 * ks][0],     s[2 * ks][1],     ph[0], pl[0]);
            split2(s[2 * ks][2],     s[2 * ks][3],     ph[1], pl[1]);
            split2(s[2 * ks + 1][0], s[2 * ks + 1][1], ph[2], pl[2]);
            split2(s[2 * ks + 1][2], s[2 * ks + 1][3], ph[3], pl[3]);
#pragma unroll
            for (int j = 0; j < 8; j++) {
                const int vo = (j * 8 + gid) * AP + ks * 32 + tid4 * 4;
                uint32_t vh[2], vl[2];
                vh[0] = *(const uint32_t*)(sm + SVH + vo);
                vh[1] = *(const uint32_t*)(sm + SVH + vo + 16);
                vl[0] = *(const uint32_t*)(sm + SVL + vo);
                vl[1] = *(const uint32_t*)(sm + SVL + vo + 16);
                mma_bf16(o[j], ph, vh);
                mma_bf16(o[j], ph, vl);
                mma_bf16(o[j], pl, vh);
            }
        }
    }

    const float i0 = 1.0f / l0s, i1 = 1.0f / l1s;
    const size_t r0 = (size_t)(bt * SEQ + q0 + wid * 16 + gid);
#pragma unroll
    for (int j = 0; j < 8; j++) {
        int col = hh * HDIM + j * 8 + tid4 * 2;
        uint32_t h, l;
        split2(o[j][0] * i0, o[j][1] * i0, h, l);
        *(uint32_t*)&Oh[r0 * DMODEL + col] = h;
        *(uint32_t*)&Ol[r0 * DMODEL + col] = l;
        split2(o[j][2] * i1, o[j][3] * i1, h, l);
        *(uint32_t*)&Oh[(r0 + 8) * DMODEL + col] = h;
        *(uint32_t*)&Ol[(r0 + 8) * DMODEL + col] = l;
    }
}

// ===========================================================================
extern "C" void kernel_launch(void* const* d_in, const int* in_sizes, int n_in,
                              void* d_out, int out_size)
{
    const float* x     = (const float*)d_in[0];
    const float* w_qkv = (const float*)d_in[1];
    const float* w_out = (const float*)d_in[2];
    const float* b_out = (const float*)d_in[3];
    float* out = (float*)d_out;

    float* qkv;
    __nv_bfloat16 *Ah, *Al, *Bh, *Bl;
    cudaGetSymbolAddress((void**)&qkv, g_qkv);
    cudaGetSymbolAddress((void**)&Ah, g_Ah);
    cudaGetSymbolAddress((void**)&Al, g_Al);
    cudaGetSymbolAddress((void**)&Bh, g_Bh);
    cudaGetSymbolAddress((void**)&Bl, g_Bl);

    cudaFuncSetAttribute(gemm_mma, cudaFuncAttributeMaxDynamicSharedMemorySize, GEMM_SMEM);
    cudaFuncSetAttribute(attn_mma, cudaFuncAttributeMaxDynamicSharedMemorySize, ATN_SMEM);

    rope_table_kernel<<<(SEQ * 32 + 255) / 256, 256>>>();

    {
        int n4 = MROWS * KDIM / 4;
        split_kernel<<<(n4 + 255) / 256, 256>>>(x, Ah, Al, n4);
        int n4b = QKVN * KDIM / 4;
        split_kernel<<<(n4b + 255) / 256, 256>>>(w_qkv, Bh, Bl, n4b);
    }

    // qkv = x @ w_qkv^T   (N = 2304 = 9 column blocks of 256)
    gemm_mma<<<dim3(QKVN / 256, MROWS / 128), 256, GEMM_SMEM>>>(
        Ah, Al, Bh, Bl, qkv, QKVN, nullptr);

    rope_apply_kernel<<<MROWS, 384>>>();

    // attention writes its output straight into the next GEMM's A buffers
    attn_mma<<<dim3(SEQ / 128, BTC * NHEADS), 256, ATN_SMEM>>>(Ah, Al);

    {
        int n4b = DMODEL * KDIM / 4;
        split_kernel<<<(n4b + 255) / 256, 256>>>(w_out, Bh, Bl, n4b);
    }
    // out = o @ w_out^T + b_out   (N = 768 = 3 column blocks of 256)
    gemm_mma<<<dim3(DMODEL / 256, MROWS / 128), 256, GEMM_SMEM>>>(
        Ah, Al, Bh, Bl, out, DMODEL, b_out);
}

// round 6
// speedup vs baseline: 10.8416x; 1.2466x over previous
#include <cuda_runtime.h>
#include <cuda_fp16.h>
#include <math.h>
#include <stdint.h>

// Problem constants
#define BTC    16
#define SEQ    1024
#define DMODEL 768
#define NHEADS 12
#define HDIM   64
#define MROWS  (BTC * SEQ)     // 16384
#define QKVN   (3 * DMODEL)    // 2304
#define KDIM   768

// Scratch (static device globals: allocation-guard safe)
__device__ float g_qkv[(size_t)MROWS * QKVN];
__device__ float g_cos[SEQ * 32];
__device__ float g_sin[SEQ * 32];
__device__ __half g_Ah[(size_t)MROWS * KDIM];    // activations, single fp16
__device__ __half g_Bh[(size_t)QKVN * KDIM];     // weights hi
__device__ __half g_Bl[(size_t)QKVN * KDIM];     // weights lo (residual)

// ===========================================================================
// Helpers
// ===========================================================================
__device__ __forceinline__ uint32_t smem_u32(const void* p) {
    uint32_t a;
    asm("{ .reg .u64 t; cvta.to.shared.u64 t, %1; cvt.u32.u64 %0, t; }" : "=r"(a) : "l"(p));
    return a;
}
#define CP16(dst, src) \
    asm volatile("cp.async.cg.shared.global [%0], [%1], 16;" :: "r"(dst), "l"(src))
#define CP_COMMIT() asm volatile("cp.async.commit_group;")
#define CP_WAIT(n)  asm volatile("cp.async.wait_group %0;" :: "n"(n))

#define LDSM4(r, a)                                                             \
    asm volatile("ldmatrix.sync.aligned.m8n8.x4.shared.b16 {%0,%1,%2,%3}, [%4];" \
        : "=r"((r)[0]), "=r"((r)[1]), "=r"((r)[2]), "=r"((r)[3]) : "r"(a))

__device__ __forceinline__ void mma_f16(float* d, const uint32_t* a, const uint32_t* b) {
    asm volatile(
        "mma.sync.aligned.m16n8k16.row.col.f32.f16.f16.f32 "
        "{%0,%1,%2,%3}, {%4,%5,%6,%7}, {%8,%9}, {%0,%1,%2,%3};"
        : "+f"(d[0]), "+f"(d[1]), "+f"(d[2]), "+f"(d[3])
        : "r"(a[0]), "r"(a[1]), "r"(a[2]), "r"(a[3]), "r"(b[0]), "r"(b[1]));
}

// pack two floats -> half2 word (x in low 16 bits)
__device__ __forceinline__ uint32_t pack_h2(float x, float y) {
    __half2 h = __floats2half2_rn(x, y);
    return *reinterpret_cast<uint32_t*>(&h);
}
// split (x,y) -> fp16 hi word + fp16 residual word
__device__ __forceinline__ void split2h(float x, float y, uint32_t& h, uint32_t& l) {
    h = pack_h2(x, y);
    __half2 hv = *reinterpret_cast<__half2*>(&h);
    l = pack_h2(x - __half2float(hv.x), y - __half2float(hv.y));
}

// ===========================================================================
// RoPE kernels
// ===========================================================================
__global__ void rope_table_kernel() {
    int idx = blockIdx.x * blockDim.x + threadIdx.x;
    if (idx >= SEQ * 32) return;
    int s = idx >> 5, p = idx & 31;
    float pos = (p < 16) ? (float)(s >> 5) : (float)(s & 31);
    int j = p & 15;
    float inv = exp2f(-(float)j * 0.8304820236903231f);
    g_cos[idx] = cosf(pos * inv);
    g_sin[idx] = sinf(pos * inv);
}

__global__ void rope_apply_kernel() {
    int n = blockIdx.x, t = threadIdx.x;
    int s = n & (SEQ - 1);
    int hh = t >> 5, p = t & 31;
    float c = g_cos[(s << 5) + p], sn = g_sin[(s << 5) + p];
    float* q = g_qkv + (size_t)n * QKVN + hh * HDIM + 2 * p;
    float2 xq = *(float2*)q;
    *(float2*)q = make_float2(xq.x * c - xq.y * sn, xq.y * c + xq.x * sn);
    float* k = q + DMODEL;
    float2 xk = *(float2*)k;
    *(float2*)k = make_float2(xk.x * c - xk.y * sn, xk.y * c + xk.x * sn);
}

// ===========================================================================
// Conversion kernels
// ===========================================================================
__global__ void conv_half_kernel(const float* __restrict__ in,
                                 __half* __restrict__ out, int n4) {
    int i = blockIdx.x * blockDim.x + threadIdx.x;
    if (i >= n4) return;
    float4 v = *(const float4*)(in + (size_t)i * 4);
    *(uint2*)(out + (size_t)i * 4) = make_uint2(pack_h2(v.x, v.y), pack_h2(v.z, v.w));
}

__global__ void splitw_kernel(const float* __restrict__ in,
                              __half* __restrict__ hi,
                              __half* __restrict__ lo, int n4) {
    int i = blockIdx.x * blockDim.x + threadIdx.x;
    if (i >= n4) return;
    float4 v = *(const float4*)(in + (size_t)i * 4);
    uint32_t h0, l0, h1, l1;
    split2h(v.x, v.y, h0, l0);
    split2h(v.z, v.w, h1, l1);
    *(uint2*)(hi + (size_t)i * 4) = make_uint2(h0, h1);
    *(uint2*)(lo + (size_t)i * 4) = make_uint2(l0, l1);
}

// ===========================================================================
// HMMA fp16 2-term GEMM: C[M,N] = A[M,768] * B[N,768]^T (+bias)
// D = Ah*(Bh + Bl); A single fp16, B split hi/lo.
// CTA tile 128(M) x 256(N), 8 warps (2m x 4n), warp tile 64x64.
// K chunked by 64, 2-stage cp.async pipeline, ldmatrix fragment loads.
// ===========================================================================
#define CHUNK 64
#define ROWB 144
#define A_TILE (128 * ROWB)            // 18432
#define B_TILE (256 * ROWB)            // 36864
#define STAGE_BYTES (A_TILE + 2 * B_TILE)   // 92160
#define OFF_A 0
#define OFF_BH A_TILE
#define OFF_BL (A_TILE + B_TILE)
#define GEMM_SMEM (2 * STAGE_BYTES)    // 184320
#define NCHUNK (KDIM / CHUNK)          // 12

__global__ __launch_bounds__(256, 1)
void gemm_mma(const __half* __restrict__ Ah,
              const __half* __restrict__ Bh, const __half* __restrict__ Bl,
              float* __restrict__ C, int N, const float* __restrict__ bias)
{
    extern __shared__ __align__(128) char sm[];
    const int t = threadIdx.x;
    const int wid = t >> 5, lane = t & 31;
    const int wm = wid & 1, wn = wid >> 1;
    const int gid = lane >> 2, tid4 = lane & 3;
    const int bm = blockIdx.y * 128;
    const int bn = blockIdx.x * 256;

    float acc[4][8][4];
#pragma unroll
    for (int i = 0; i < 4; i++)
#pragma unroll
        for (int j = 0; j < 8; j++)
#pragma unroll
            for (int k = 0; k < 4; k++) acc[i][j][k] = 0.0f;

    const uint32_t smb = smem_u32(sm);
    const uint32_t aoff = (uint32_t)((wm * 64 + (lane & 15)) * ROWB + ((lane >> 4) & 1) * 16);
    const uint32_t boff = (uint32_t)((wn * 64 + (lane & 7) + ((lane >> 4) & 1) * 8) * ROWB +
                                     ((lane >> 3) & 1) * 16);

    auto issue_copy = [&](int c) {
        char* dst0 = sm + (c & 1) * STAGE_BYTES;
        const int k0 = c * CHUNK;
#pragma unroll
        for (int i = 0; i < 20; i++) {
            int idx = i * 256 + t;             // 5120 segments of 16B
            uint32_t d;
            const __half* s;
            if (idx < 1024) {                   // A
                int row = idx >> 3, g = idx & 7;
                d = smem_u32(dst0 + OFF_A + row * ROWB + g * 16);
                s = Ah + (size_t)(bm + row) * KDIM + k0 + g * 8;
            } else {                            // B hi | lo
                int j = idx - 1024;             // 0..4095
                int half = j >> 11;
                int row = (j & 2047) >> 3, g = j & 7;
                d = smem_u32(dst0 + (half ? OFF_BL : OFF_BH) + row * ROWB + g * 16);
                s = (half ? Bl : Bh) + (size_t)(bn + row) * KDIM + k0 + g * 8;
            }
            CP16(d, s);
        }
        CP_COMMIT();
    };

    issue_copy(0);

    for (int c = 0; c < NCHUNK; c++) {
        if (c + 1 < NCHUNK) {
            issue_copy(c + 1);
            CP_WAIT(1);
        } else {
            CP_WAIT(0);
        }
        __syncthreads();

        const uint32_t sb = smb + (c & 1) * STAGE_BYTES;

#pragma unroll
        for (int ks = 0; ks < 4; ks++) {
            uint32_t ah[4][4];
#pragma unroll
            for (int mi = 0; mi < 4; mi++) {
                uint32_t a = sb + aoff + mi * (16 * ROWB) + ks * 32;
                LDSM4(ah[mi], a + OFF_A);
            }
#pragma unroll
            for (int h = 0; h < 2; h++) {
                uint32_t t0[4], t1[4], u0[4], u1[4];
                uint32_t b0 = sb + boff + (h * 32) * ROWB + ks * 32;
                uint32_t b1 = b0 + 16 * ROWB;
                LDSM4(t0, b0 + OFF_BH);
                LDSM4(t1, b1 + OFF_BH);
                LDSM4(u0, b0 + OFF_BL);
                LDSM4(u1, b1 + OFF_BL);
                uint32_t bh[4][2] = {{t0[0], t0[1]}, {t0[2], t0[3]},
                                     {t1[0], t1[1]}, {t1[2], t1[3]}};
                uint32_t bl[4][2] = {{u0[0], u0[1]}, {u0[2], u0[3]},
                                     {u1[0], u1[1]}, {u1[2], u1[3]}};
#pragma unroll
                for (int mi = 0; mi < 4; mi++)
#pragma unroll
                    for (int ni = 0; ni < 4; ni++) {
                        float* d = acc[mi][h * 4 + ni];
                        mma_f16(d, ah[mi], bh[ni]);
                        mma_f16(d, ah[mi], bl[ni]);
                    }
            }
        }
        __syncthreads();
    }

    // epilogue
#pragma unroll
    for (int mi = 0; mi < 4; mi++) {
        int r0 = bm + wm * 64 + mi * 16 + gid;
#pragma unroll
        for (int ni = 0; ni < 8; ni++) {
            int cc = bn + wn * 64 + ni * 8 + tid4 * 2;
            float2 v0 = make_float2(acc[mi][ni][0], acc[mi][ni][1]);
            float2 v1 = make_float2(acc[mi][ni][2], acc[mi][ni][3]);
            if (bias) {
                float2 bv = *(const float2*)&bias[cc];
                v0.x += bv.x; v0.y += bv.y;
                v1.x += bv.x; v1.y += bv.y;
            }
            *(float2*)&C[(size_t)r0 * N + cc]       = v0;
            *(float2*)&C[(size_t)(r0 + 8) * N + cc] = v1;
        }
    }
}

// ===========================================================================
// HMMA fp16 2-term flash attention.
// grid=(8, 192), block=256 (8 warps). CTA: 128 q-rows; kv tiles of 64.
// S = Qh*(Kh+Kl), O += Ph*(Vh+Vl); Q and P single fp16, K/V split hi/lo.
// Epilogue writes single fp16 O directly into the out-projection A buffer.
// ===========================================================================
#define AP 144
#define SQ  0
#define SKH (SQ + 128 * AP)           // 18432
#define SKL (SKH + 64 * AP)           // 27648
#define SVH (SKL + 64 * AP)           // 36864
#define SVL (SVH + 64 * AP)           // 46080
#define ATN_SMEM (SVL + 64 * AP)      // 55296

__global__ __launch_bounds__(256)
void attn_mma(__half* __restrict__ Oh)
{
    extern __shared__ __align__(16) char sm[];
    const int bh = blockIdx.y;
    const int bt = bh / NHEADS;
    const int hh = bh % NHEADS;
    const int q0 = blockIdx.x * 128;
    const int t = threadIdx.x;
    const int wid = t >> 5, lane = t & 31;
    const int gid = lane >> 2, tid4 = lane & 3;

    const float* qg = g_qkv + (size_t)(bt * SEQ + q0) * QKVN + hh * HDIM;

    // ---- load Q (once), scale 1/8, convert to fp16 ----
#pragma unroll
    for (int i = 0; i < 8; i++) {
        int w = t + 256 * i;               // 2048 items = 128 rows x 16 dgroups
        int dg = w & 15, row = w >> 4;
        float4 v = *(const float4*)(qg + (size_t)row * QKVN + dg * 4);
        v.x *= 0.125f; v.y *= 0.125f; v.z *= 0.125f; v.w *= 0.125f;
        *(uint2*)(sm + SQ + row * AP + dg * 8) =
            make_uint2(pack_h2(v.x, v.y), pack_h2(v.z, v.w));
    }

    float m0 = -1e30f, m1 = -1e30f, l0s = 0.0f, l1s = 0.0f;
    float o[8][4];
#pragma unroll
    for (int j = 0; j < 8; j++)
#pragma unroll
        for (int k = 0; k < 4; k++) o[j][k] = 0.0f;

    const int qrb = wid * 16 + gid;

    for (int kt = 0; kt < SEQ / 64; kt++) {
        __syncthreads();
        // ---- K tile (natural kv,d), fp16 split hi/lo ----
        const float* kg = g_qkv + (size_t)(bt * SEQ + kt * 64) * QKVN + DMODEL + hh * HDIM;
#pragma unroll
        for (int i = 0; i < 4; i++) {
            int w = t + 256 * i;           // 1024 items = 64 kv x 16 dgroups
            int dg = w & 15, kv = w >> 4;
            float4 v = *(const float4*)(kg + (size_t)kv * QKVN + dg * 4);
            uint32_t h0, l0, h1, l1;
            split2h(v.x, v.y, h0, l0);
            split2h(v.z, v.w, h1, l1);
            *(uint2*)(sm + SKH + kv * AP + dg * 8) = make_uint2(h0, h1);
            *(uint2*)(sm + SKL + kv * AP + dg * 8) = make_uint2(l0, l1);
        }
        // ---- V tile transposed (col, kv), fp16 split hi/lo ----
        const float* vg = g_qkv + (size_t)(bt * SEQ + kt * 64) * QKVN + 2 * DMODEL + hh * HDIM;
#pragma unroll
        for (int i = 0; i < 2; i++) {
            int w = t + 256 * i;           // 512 items = 32 kv-pairs x 16 cgroups
            int kvp = w & 31, cg = w >> 5;
            int kv0 = kvp * 2;
            float4 va = *(const float4*)(vg + (size_t)kv0 * QKVN + cg * 4);
            float4 vb = *(const float4*)(vg + (size_t)(kv0 + 1) * QKVN + cg * 4);
            const float ax[4] = {va.x, va.y, va.z, va.w};
            const float bx[4] = {vb.x, vb.y, vb.z, vb.w};
#pragma unroll
            for (int jj = 0; jj < 4; jj++) {
                uint32_t h, l;
                split2h(ax[jj], bx[jj], h, l);
                *(uint32_t*)(sm + SVH + (cg * 4 + jj) * AP + kv0 * 2) = h;
                *(uint32_t*)(sm + SVL + (cg * 4 + jj) * AP + kv0 * 2) = l;
            }
        }
        __syncthreads();

        // ---- S = Q K^T (2-term) ----
        float s[8][4];
#pragma unroll
        for (int j = 0; j < 8; j++)
#pragma unroll
            for (int k = 0; k < 4; k++) s[j][k] = 0.0f;

#pragma unroll
        for (int ks = 0; ks < 4; ks++) {
            const int qo = qrb * AP + ks * 32 + tid4 * 4;
            uint32_t ah[4];
            ah[0] = *(const uint32_t*)(sm + SQ + qo);
            ah[1] = *(const uint32_t*)(sm + SQ + qo + 8 * AP);
            ah[2] = *(const uint32_t*)(sm + SQ + qo + 16);
            ah[3] = *(const uint32_t*)(sm + SQ + qo + 8 * AP + 16);
#pragma unroll
            for (int j = 0; j < 8; j++) {
                const int ko = (j * 8 + gid) * AP + ks * 32 + tid4 * 4;
                uint32_t kb[2], kl[2];
                kb[0] = *(const uint32_t*)(sm + SKH + ko);
                kb[1] = *(const uint32_t*)(sm + SKH + ko + 16);
                kl[0] = *(const uint32_t*)(sm + SKL + ko);
                kl[1] = *(const uint32_t*)(sm + SKL + ko + 16);
                mma_f16(s[j], ah, kb);
                mma_f16(s[j], ah, kl);
            }
        }

        // ---- online softmax ----
        float mt0 = -1e30f, mt1 = -1e30f;
#pragma unroll
        for (int j = 0; j < 8; j++) {
            mt0 = fmaxf(mt0, fmaxf(s[j][0], s[j][1]));
            mt1 = fmaxf(mt1, fmaxf(s[j][2], s[j][3]));
        }
        mt0 = fmaxf(mt0, __shfl_xor_sync(0xffffffffu, mt0, 1));
        mt0 = fmaxf(mt0, __shfl_xor_sync(0xffffffffu, mt0, 2));
        mt1 = fmaxf(mt1, __shfl_xor_sync(0xffffffffu, mt1, 1));
        mt1 = fmaxf(mt1, __shfl_xor_sync(0xffffffffu, mt1, 2));
        float mn0 = fmaxf(m0, mt0), mn1 = fmaxf(m1, mt1);
        float a0 = __expf(m0 - mn0), a1 = __expf(m1 - mn1);
        m0 = mn0; m1 = mn1;
        float ps0 = 0.0f, ps1 = 0.0f;
#pragma unroll
        for (int j = 0; j < 8; j++) {
            s[j][0] = __expf(s[j][0] - m0);
            s[j][1] = __expf(s[j][1] - m0);
            s[j][2] = __expf(s[j][2] - m1);
            s[j][3] = __expf(s[j][3] - m1);
            ps0 += s[j][0] + s[j][1];
            ps1 += s[j][2] + s[j][3];
        }
        ps0 += __shfl_xor_sync(0xffffffffu, ps0, 1);
        ps0 += __shfl_xor_sync(0xffffffffu, ps0, 2);
        ps1 += __shfl_xor_sync(0xffffffffu, ps1, 1);
        ps1 += __shfl_xor_sync(0xffffffffu, ps1, 2);
        l0s = l0s * a0 + ps0;
        l1s = l1s * a1 + ps1;
#pragma unroll
        for (int j = 0; j < 8; j++) {
            o[j][0] *= a0; o[j][1] *= a0;
            o[j][2] *= a1; o[j][3] *= a1;
        }

        // ---- O += P V (2-term; P single fp16 from S fragments) ----
#pragma unroll
        for (int ks = 0; ks < 4; ks++) {
            uint32_t ph[4];
            ph[0] = pack_h2(s[2 * ks][0],     s[2 * ks][1]);
            ph[1] = pack_h2(s[2 * ks][2],     s[2 * ks][3]);
            ph[2] = pack_h2(s[2 * ks + 1][0], s[2 * ks + 1][1]);
            ph[3] = pack_h2(s[2 * ks + 1][2], s[2 * ks + 1][3]);
#pragma unroll
            for (int j = 0; j < 8; j++) {
                const int vo = (j * 8 + gid) * AP + ks * 32 + tid4 * 4;
                uint32_t vh[2], vl[2];
                vh[0] = *(const uint32_t*)(sm + SVH + vo);
                vh[1] = *(const uint32_t*)(sm + SVH + vo + 16);
                vl[0] = *(const uint32_t*)(sm + SVL + vo);
                vl[1] = *(const uint32_t*)(sm + SVL + vo + 16);
                mma_f16(o[j], ph, vh);
                mma_f16(o[j], ph, vl);
            }
        }
    }

    // ---- epilogue: normalize and write single fp16 ----
    const float i0 = 1.0f / l0s, i1 = 1.0f / l1s;
    const size_t r0 = (size_t)(bt * SEQ + q0 + wid * 16 + gid);
#pragma unroll
    for (int j = 0; j < 8; j++) {
        int col = hh * HDIM + j * 8 + tid4 * 2;
        *(uint32_t*)&Oh[r0 * DMODEL + col]       = pack_h2(o[j][0] * i0, o[j][1] * i0);
        *(uint32_t*)&Oh[(r0 + 8) * DMODEL + col] = pack_h2(o[j][2] * i1, o[j][3] * i1);
    }
}

// ===========================================================================
extern "C" void kernel_launch(void* const* d_in, const int* in_sizes, int n_in,
                              void* d_out, int out_size)
{
    const float* x     = (const float*)d_in[0];
    const float* w_qkv = (const float*)d_in[1];
    const float* w_out = (const float*)d_in[2];
    const float* b_out = (const float*)d_in[3];
    float* out = (float*)d_out;

    float* qkv;
    __half *Ah, *Bh, *Bl;
    cudaGetSymbolAddress((void**)&qkv, g_qkv);
    cudaGetSymbolAddress((void**)&Ah, g_Ah);
    cudaGetSymbolAddress((void**)&Bh, g_Bh);
    cudaGetSymbolAddress((void**)&Bl, g_Bl);

    cudaFuncSetAttribute(gemm_mma, cudaFuncAttributeMaxDynamicSharedMemorySize, GEMM_SMEM);
    cudaFuncSetAttribute(attn_mma, cudaFuncAttributeMaxDynamicSharedMemorySize, ATN_SMEM);

    rope_table_kernel<<<(SEQ * 32 + 255) / 256, 256>>>();

    {
        int n4 = MROWS * KDIM / 4;
        conv_half_kernel<<<(n4 + 255) / 256, 256>>>(x, Ah, n4);
        int n4b = QKVN * KDIM / 4;
        splitw_kernel<<<(n4b + 255) / 256, 256>>>(w_qkv, Bh, Bl, n4b);
    }

    // qkv = x @ w_qkv^T
    gemm_mma<<<dim3(QKVN / 256, MROWS / 128), 256, GEMM_SMEM>>>(
        Ah, Bh, Bl, qkv, QKVN, nullptr);

    rope_apply_kernel<<<MROWS, 384>>>();

    // attention writes fp16 output straight into the next GEMM's A buffer
    attn_mma<<<dim3(SEQ / 128, BTC * NHEADS), 256, ATN_SMEM>>>(Ah);

    {
        int n4b = DMODEL * KDIM / 4;
        splitw_kernel<<<(n4b + 255) / 256, 256>>>(w_out, Bh, Bl, n4b);
    }
    // out = o @ w_out^T + b_out
    gemm_mma<<<dim3(DMODEL / 256, MROWS / 128), 256, GEMM_SMEM>>>(
        Ah, Bh, Bl, out, DMODEL, b_out);
}

// round 7
// speedup vs baseline: 11.7419x; 1.0830x over previous
#include <cuda_runtime.h>
#include <cuda_fp16.h>
#include <math.h>
#include <stdint.h>

// Problem constants
#define BTC    16
#define SEQ    1024
#define DMODEL 768
#define NHEADS 12
#define HDIM   64
#define MROWS  (BTC * SEQ)     // 16384
#define QKVN   (3 * DMODEL)    // 2304
#define KDIM   768

// Scratch (static device globals: allocation-guard safe)
__device__ float g_qkv[(size_t)MROWS * QKVN];
__device__ float g_cos[SEQ * 32];
__device__ float g_sin[SEQ * 32];
__device__ __half g_Ah[(size_t)MROWS * KDIM];    // activations, single fp16
__device__ __half g_Bh[(size_t)QKVN * KDIM];     // weights hi
__device__ __half g_Bl[(size_t)QKVN * KDIM];     // weights lo (residual)

// ===========================================================================
// Helpers
// ===========================================================================
__device__ __forceinline__ uint32_t smem_u32(const void* p) {
    uint32_t a;
    asm("{ .reg .u64 t; cvta.to.shared.u64 t, %1; cvt.u32.u64 %0, t; }" : "=r"(a) : "l"(p));
    return a;
}
#define CP16(dst, src) \
    asm volatile("cp.async.cg.shared.global [%0], [%1], 16;" :: "r"(dst), "l"(src))
#define CP_COMMIT() asm volatile("cp.async.commit_group;")
#define CP_WAIT(n)  asm volatile("cp.async.wait_group %0;" :: "n"(n))

#define LDSM4(r, a)                                                             \
    asm volatile("ldmatrix.sync.aligned.m8n8.x4.shared.b16 {%0,%1,%2,%3}, [%4];" \
        : "=r"((r)[0]), "=r"((r)[1]), "=r"((r)[2]), "=r"((r)[3]) : "r"(a))

__device__ __forceinline__ void mma_f16(float* d, const uint32_t* a, const uint32_t* b) {
    asm volatile(
        "mma.sync.aligned.m16n8k16.row.col.f32.f16.f16.f32 "
        "{%0,%1,%2,%3}, {%4,%5,%6,%7}, {%8,%9}, {%0,%1,%2,%3};"
        : "+f"(d[0]), "+f"(d[1]), "+f"(d[2]), "+f"(d[3])
        : "r"(a[0]), "r"(a[1]), "r"(a[2]), "r"(a[3]), "r"(b[0]), "r"(b[1]));
}

// pack two floats -> half2 word (x in low 16 bits)
__device__ __forceinline__ uint32_t pack_h2(float x, float y) {
    __half2 h = __floats2half2_rn(x, y);
    return *reinterpret_cast<uint32_t*>(&h);
}
// split (x,y) -> fp16 hi word + fp16 residual word
__device__ __forceinline__ void split2h(float x, float y, uint32_t& h, uint32_t& l) {
    h = pack_h2(x, y);
    __half2 hv = *reinterpret_cast<__half2*>(&h);
    l = pack_h2(x - __half2float(hv.x), y - __half2float(hv.y));
}

// ===========================================================================
// RoPE kernels
// ===========================================================================
__global__ void rope_table_kernel() {
    int idx = blockIdx.x * blockDim.x + threadIdx.x;
    if (idx >= SEQ * 32) return;
    int s = idx >> 5, p = idx & 31;
    float pos = (p < 16) ? (float)(s >> 5) : (float)(s & 31);
    int j = p & 15;
    float inv = exp2f(-(float)j * 0.8304820236903231f);
    g_cos[idx] = cosf(pos * inv);
    g_sin[idx] = sinf(pos * inv);
}

__global__ void rope_apply_kernel() {
    int n = blockIdx.x, t = threadIdx.x;
    int s = n & (SEQ - 1);
    int hh = t >> 5, p = t & 31;
    float c = g_cos[(s << 5) + p], sn = g_sin[(s << 5) + p];
    float* q = g_qkv + (size_t)n * QKVN + hh * HDIM + 2 * p;
    float2 xq = *(float2*)q;
    *(float2*)q = make_float2(xq.x * c - xq.y * sn, xq.y * c + xq.x * sn);
    float* k = q + DMODEL;
    float2 xk = *(float2*)k;
    *(float2*)k = make_float2(xk.x * c - xk.y * sn, xk.y * c + xk.x * sn);
}

// ===========================================================================
// Conversion kernels
// ===========================================================================
__global__ void conv_half_kernel(const float* __restrict__ in,
                                 __half* __restrict__ out, int n4) {
    int i = blockIdx.x * blockDim.x + threadIdx.x;
    if (i >= n4) return;
    float4 v = *(const float4*)(in + (size_t)i * 4);
    *(uint2*)(out + (size_t)i * 4) = make_uint2(pack_h2(v.x, v.y), pack_h2(v.z, v.w));
}

__global__ void splitw_kernel(const float* __restrict__ in,
                              __half* __restrict__ hi,
                              __half* __restrict__ lo, int n4) {
    int i = blockIdx.x * blockDim.x + threadIdx.x;
    if (i >= n4) return;
    float4 v = *(const float4*)(in + (size_t)i * 4);
    uint32_t h0, l0, h1, l1;
    split2h(v.x, v.y, h0, l0);
    split2h(v.z, v.w, h1, l1);
    *(uint2*)(hi + (size_t)i * 4) = make_uint2(h0, h1);
    *(uint2*)(lo + (size_t)i * 4) = make_uint2(l0, l1);
}

// ===========================================================================
// HMMA fp16 2-term GEMM: C[M,N] = A[M,768] * B[N,768]^T (+bias)
// D = Ah*(Bh + Bl); A single fp16, B split hi/lo.
// CTA tile 128x128, 8 warps (2m x 4n), warp tile 64x32, 2 CTAs/SM.
// K chunked by 64, 2-stage cp.async pipeline, ldmatrix fragment loads.
// ===========================================================================
#define CHUNK 64
#define ROWB 144
#define A_TILE (128 * ROWB)            // 18432
#define B_TILE (128 * ROWB)            // 18432 (each of hi/lo)
#define STAGE_BYTES (A_TILE + 2 * B_TILE)   // 55296
#define OFF_A 0
#define OFF_BH A_TILE
#define OFF_BL (A_TILE + B_TILE)
#define GEMM_SMEM (2 * STAGE_BYTES)    // 110592
#define NCHUNK (KDIM / CHUNK)          // 12

__global__ __launch_bounds__(256, 2)
void gemm_mma(const __half* __restrict__ Ah,
              const __half* __restrict__ Bh, const __half* __restrict__ Bl,
              float* __restrict__ C, int N, const float* __restrict__ bias)
{
    extern __shared__ __align__(128) char sm[];
    const int t = threadIdx.x;
    const int wid = t >> 5, lane = t & 31;
    const int wm = wid & 1, wn = wid >> 1;
    const int gid = lane >> 2, tid4 = lane & 3;
    const int bm = blockIdx.y * 128;
    const int bn = blockIdx.x * 128;

    float acc[4][4][4];
#pragma unroll
    for (int i = 0; i < 4; i++)
#pragma unroll
        for (int j = 0; j < 4; j++)
#pragma unroll
            for (int k = 0; k < 4; k++) acc[i][j][k] = 0.0f;

    const uint32_t smb = smem_u32(sm);
    const uint32_t aoff = (uint32_t)((wm * 64 + (lane & 15)) * ROWB + ((lane >> 4) & 1) * 16);
    const uint32_t boff = (uint32_t)((wn * 32 + (lane & 7) + ((lane >> 4) & 1) * 8) * ROWB +
                                     ((lane >> 3) & 1) * 16);

    auto issue_copy = [&](int c) {
        char* dst0 = sm + (c & 1) * STAGE_BYTES;
        const int k0 = c * CHUNK;
#pragma unroll
        for (int i = 0; i < 12; i++) {
            int idx = i * 256 + t;             // 3072 segments of 16B
            int tile = idx >> 10;              // 0=A, 1=Bh, 2=Bl
            int rem = idx & 1023;
            int row = rem >> 3, g = rem & 7;
            uint32_t d = smem_u32(dst0 + tile * 18432 + row * ROWB + g * 16);
            const __half* s;
            if (tile == 0)      s = Ah + (size_t)(bm + row) * KDIM + k0 + g * 8;
            else if (tile == 1) s = Bh + (size_t)(bn + row) * KDIM + k0 + g * 8;
            else                s = Bl + (size_t)(bn + row) * KDIM + k0 + g * 8;
            CP16(d, s);
        }
        CP_COMMIT();
    };

    issue_copy(0);

    for (int c = 0; c < NCHUNK; c++) {
        if (c + 1 < NCHUNK) {
            issue_copy(c + 1);
            CP_WAIT(1);
        } else {
            CP_WAIT(0);
        }
        __syncthreads();

        const uint32_t sb = smb + (c & 1) * STAGE_BYTES;

#pragma unroll
        for (int ks = 0; ks < 4; ks++) {
            uint32_t ah[4][4];
#pragma unroll
            for (int mi = 0; mi < 4; mi++) {
                uint32_t a = sb + aoff + mi * (16 * ROWB) + ks * 32;
                LDSM4(ah[mi], a + OFF_A);
            }
            uint32_t t0[4], t1[4], u0[4], u1[4];
            uint32_t b0 = sb + boff + ks * 32;
            uint32_t b1 = b0 + 16 * ROWB;
            LDSM4(t0, b0 + OFF_BH);
            LDSM4(t1, b1 + OFF_BH);
            LDSM4(u0, b0 + OFF_BL);
            LDSM4(u1, b1 + OFF_BL);
            uint32_t bh[4][2] = {{t0[0], t0[1]}, {t0[2], t0[3]},
                                 {t1[0], t1[1]}, {t1[2], t1[3]}};
            uint32_t bl[4][2] = {{u0[0], u0[1]}, {u0[2], u0[3]},
                                 {u1[0], u1[1]}, {u1[2], u1[3]}};
#pragma unroll
            for (int mi = 0; mi < 4; mi++)
#pragma unroll
                for (int ni = 0; ni < 4; ni++) {
                    float* d = acc[mi][ni];
                    mma_f16(d, ah[mi], bh[ni]);
                    mma_f16(d, ah[mi], bl[ni]);
                }
        }
        __syncthreads();
    }

    // epilogue
#pragma unroll
    for (int mi = 0; mi < 4; mi++) {
        int r0 = bm + wm * 64 + mi * 16 + gid;
#pragma unroll
        for (int ni = 0; ni < 4; ni++) {
            int cc = bn + wn * 32 + ni * 8 + tid4 * 2;
            float2 v0 = make_float2(acc[mi][ni][0], acc[mi][ni][1]);
            float2 v1 = make_float2(acc[mi][ni][2], acc[mi][ni][3]);
            if (bias) {
                float2 bv = *(const float2*)&bias[cc];
                v0.x += bv.x; v0.y += bv.y;
                v1.x += bv.x; v1.y += bv.y;
            }
            *(float2*)&C[(size_t)r0 * N + cc]       = v0;
            *(float2*)&C[(size_t)(r0 + 8) * N + cc] = v1;
        }
    }
}

// ===========================================================================
// HMMA fp16 2-term flash attention, 2 CTAs/SM.
// grid=(8, 192), block=256 (8 warps). CTA: 128 q-rows; kv tiles of 64.
// S = Qh*(Kh+Kl), O += Ph*(Vh+Vl); Q and P single fp16, K/V split hi/lo.
// ===========================================================================
#define AP 144
#define SQ  0
#define SKH (SQ + 128 * AP)           // 18432
#define SKL (SKH + 64 * AP)           // 27648
#define SVH (SKL + 64 * AP)           // 36864
#define SVL (SVH + 64 * AP)           // 46080
#define ATN_SMEM (SVL + 64 * AP)      // 55296

__global__ __launch_bounds__(256, 2)
void attn_mma(__half* __restrict__ Oh)
{
    extern __shared__ __align__(16) char sm[];
    const int bh = blockIdx.y;
    const int bt = bh / NHEADS;
    const int hh = bh % NHEADS;
    const int q0 = blockIdx.x * 128;
    const int t = threadIdx.x;
    const int wid = t >> 5, lane = t & 31;
    const int gid = lane >> 2, tid4 = lane & 3;

    const float* qg = g_qkv + (size_t)(bt * SEQ + q0) * QKVN + hh * HDIM;

    // ---- load Q (once), scale 1/8, convert to fp16 ----
#pragma unroll
    for (int i = 0; i < 8; i++) {
        int w = t + 256 * i;               // 2048 items = 128 rows x 16 dgroups
        int dg = w & 15, row = w >> 4;
        float4 v = *(const float4*)(qg + (size_t)row * QKVN + dg * 4);
        v.x *= 0.125f; v.y *= 0.125f; v.z *= 0.125f; v.w *= 0.125f;
        *(uint2*)(sm + SQ + row * AP + dg * 8) =
            make_uint2(pack_h2(v.x, v.y), pack_h2(v.z, v.w));
    }

    float m0 = -1e30f, m1 = -1e30f, l0s = 0.0f, l1s = 0.0f;
    float o[8][4];
#pragma unroll
    for (int j = 0; j < 8; j++)
#pragma unroll
        for (int k = 0; k < 4; k++) o[j][k] = 0.0f;

    const int qrb = wid * 16 + gid;

    for (int kt = 0; kt < SEQ / 64; kt++) {
        __syncthreads();
        // ---- K tile (natural kv,d), fp16 split hi/lo ----
        const float* kg = g_qkv + (size_t)(bt * SEQ + kt * 64) * QKVN + DMODEL + hh * HDIM;
#pragma unroll
        for (int i = 0; i < 4; i++) {
            int w = t + 256 * i;           // 1024 items = 64 kv x 16 dgroups
            int dg = w & 15, kv = w >> 4;
            float4 v = *(const float4*)(kg + (size_t)kv * QKVN + dg * 4);
            uint32_t h0, l0, h1, l1;
            split2h(v.x, v.y, h0, l0);
            split2h(v.z, v.w, h1, l1);
            *(uint2*)(sm + SKH + kv * AP + dg * 8) = make_uint2(h0, h1);
            *(uint2*)(sm + SKL + kv * AP + dg * 8) = make_uint2(l0, l1);
        }
        // ---- V tile transposed (col, kv), fp16 split hi/lo ----
        const float* vg = g_qkv + (size_t)(bt * SEQ + kt * 64) * QKVN + 2 * DMODEL + hh * HDIM;
#pragma unroll
        for (int i = 0; i < 2; i++) {
            int w = t + 256 * i;           // 512 items = 32 kv-pairs x 16 cgroups
            int kvp = w & 31, cg = w >> 5;
            int kv0 = kvp * 2;
            float4 va = *(const float4*)(vg + (size_t)kv0 * QKVN + cg * 4);
            float4 vb = *(const float4*)(vg + (size_t)(kv0 + 1) * QKVN + cg * 4);
            const float ax[4] = {va.x, va.y, va.z, va.w};
            const float bx[4] = {vb.x, vb.y, vb.z, vb.w};
#pragma unroll
            for (int jj = 0; jj < 4; jj++) {
                uint32_t h, l;
                split2h(ax[jj], bx[jj], h, l);
                *(uint32_t*)(sm + SVH + (cg * 4 + jj) * AP + kv0 * 2) = h;
                *(uint32_t*)(sm + SVL + (cg * 4 + jj) * AP + kv0 * 2) = l;
            }
        }
        __syncthreads();

        // ---- S = Q K^T (2-term) ----
        float s[8][4];
#pragma unroll
        for (int j = 0; j < 8; j++)
#pragma unroll
            for (int k = 0; k < 4; k++) s[j][k] = 0.0f;

#pragma unroll
        for (int ks = 0; ks < 4; ks++) {
            const int qo = qrb * AP + ks * 32 + tid4 * 4;
            uint32_t ah[4];
            ah[0] = *(const uint32_t*)(sm + SQ + qo);
            ah[1] = *(const uint32_t*)(sm + SQ + qo + 8 * AP);
            ah[2] = *(const uint32_t*)(sm + SQ + qo + 16);
            ah[3] = *(const uint32_t*)(sm + SQ + qo + 8 * AP + 16);
#pragma unroll
            for (int j = 0; j < 8; j++) {
                const int ko = (j * 8 + gid) * AP + ks * 32 + tid4 * 4;
                uint32_t kb[2], kl[2];
                kb[0] = *(const uint32_t*)(sm + SKH + ko);
                kb[1] = *(const uint32_t*)(sm + SKH + ko + 16);
                kl[0] = *(const uint32_t*)(sm + SKL + ko);
                kl[1] = *(const uint32_t*)(sm + SKL + ko + 16);
                mma_f16(s[j], ah, kb);
                mma_f16(s[j], ah, kl);
            }
        }

        // ---- online softmax ----
        float mt0 = -1e30f, mt1 = -1e30f;
#pragma unroll
        for (int j = 0; j < 8; j++) {
            mt0 = fmaxf(mt0, fmaxf(s[j][0], s[j][1]));
            mt1 = fmaxf(mt1, fmaxf(s[j][2], s[j][3]));
        }
        mt0 = fmaxf(mt0, __shfl_xor_sync(0xffffffffu, mt0, 1));
        mt0 = fmaxf(mt0, __shfl_xor_sync(0xffffffffu, mt0, 2));
        mt1 = fmaxf(mt1, __shfl_xor_sync(0xffffffffu, mt1, 1));
        mt1 = fmaxf(mt1, __shfl_xor_sync(0xffffffffu, mt1, 2));
        float mn0 = fmaxf(m0, mt0), mn1 = fmaxf(m1, mt1);
        float a0 = __expf(m0 - mn0), a1 = __expf(m1 - mn1);
        m0 = mn0; m1 = mn1;
        float ps0 = 0.0f, ps1 = 0.0f;
#pragma unroll
        for (int j = 0; j < 8; j++) {
            s[j][0] = __expf(s[j][0] - m0);
            s[j][1] = __expf(s[j][1] - m0);
            s[j][2] = __expf(s[j][2] - m1);
            s[j][3] = __expf(s[j][3] - m1);
            ps0 += s[j][0] + s[j][1];
            ps1 += s[j][2] + s[j][3];
        }
        ps0 += __shfl_xor_sync(0xffffffffu, ps0, 1);
        ps0 += __shfl_xor_sync(0xffffffffu, ps0, 2);
        ps1 += __shfl_xor_sync(0xffffffffu, ps1, 1);
        ps1 += __shfl_xor_sync(0xffffffffu, ps1, 2);
        l0s = l0s * a0 + ps0;
        l1s = l1s * a1 + ps1;
#pragma unroll
        for (int j = 0; j < 8; j++) {
            o[j][0] *= a0; o[j][1] *= a0;
            o[j][2] *= a1; o[j][3] *= a1;
        }

        // ---- O += P V (2-term; P single fp16 from S fragments) ----
#pragma unroll
        for (int ks = 0; ks < 4; ks++) {
            uint32_t ph[4];
            ph[0] = pack_h2(s[2 * ks][0],     s[2 * ks][1]);
            ph[1] = pack_h2(s[2 * ks][2],     s[2 * ks][3]);
            ph[2] = pack_h2(s[2 * ks + 1][0], s[2 * ks + 1][1]);
            ph[3] = pack_h2(s[2 * ks + 1][2], s[2 * ks + 1][3]);
#pragma unroll
            for (int j = 0; j < 8; j++) {
                const int vo = (j * 8 + gid) * AP + ks * 32 + tid4 * 4;
                uint32_t vh[2], vl[2];
                vh[0] = *(const uint32_t*)(sm + SVH + vo);
                vh[1] = *(const uint32_t*)(sm + SVH + vo + 16);
                vl[0] = *(const uint32_t*)(sm + SVL + vo);
                vl[1] = *(const uint32_t*)(sm + SVL + vo + 16);
                mma_f16(o[j], ph, vh);
                mma_f16(o[j], ph, vl);
            }
        }
    }

    // ---- epilogue: normalize and write single fp16 ----
    const float i0 = 1.0f / l0s, i1 = 1.0f / l1s;
    const size_t r0 = (size_t)(bt * SEQ + q0 + wid * 16 + gid);
#pragma unroll
    for (int j = 0; j < 8; j++) {
        int col = hh * HDIM + j * 8 + tid4 * 2;
        *(uint32_t*)&Oh[r0 * DMODEL + col]       = pack_h2(o[j][0] * i0, o[j][1] * i0);
        *(uint32_t*)&Oh[(r0 + 8) * DMODEL + col] = pack_h2(o[j][2] * i1, o[j][3] * i1);
    }
}

// ===========================================================================
extern "C" void kernel_launch(void* const* d_in, const int* in_sizes, int n_in,
                              void* d_out, int out_size)
{
    const float* x     = (const float*)d_in[0];
    const float* w_qkv = (const float*)d_in[1];
    const float* w_out = (const float*)d_in[2];
    const float* b_out = (const float*)d_in[3];
    float* out = (float*)d_out;

    float* qkv;
    __half *Ah, *Bh, *Bl;
    cudaGetSymbolAddress((void**)&qkv, g_qkv);
    cudaGetSymbolAddress((void**)&Ah, g_Ah);
    cudaGetSymbolAddress((void**)&Bh, g_Bh);
    cudaGetSymbolAddress((void**)&Bl, g_Bl);

    cudaFuncSetAttribute(gemm_mma, cudaFuncAttributeMaxDynamicSharedMemorySize, GEMM_SMEM);
    cudaFuncSetAttribute(attn_mma, cudaFuncAttributeMaxDynamicSharedMemorySize, ATN_SMEM);

    rope_table_kernel<<<(SEQ * 32 + 255) / 256, 256>>>();

    {
        int n4 = MROWS * KDIM / 4;
        conv_half_kernel<<<(n4 + 255) / 256, 256>>>(x, Ah, n4);
        int n4b = QKVN * KDIM / 4;
        splitw_kernel<<<(n4b + 255) / 256, 256>>>(w_qkv, Bh, Bl, n4b);
    }

    // qkv = x @ w_qkv^T
    gemm_mma<<<dim3(QKVN / 128, MROWS / 128), 256, GEMM_SMEM>>>(
        Ah, Bh, Bl, qkv, QKVN, nullptr);

    rope_apply_kernel<<<MROWS, 384>>>();

    // attention writes fp16 output straight into the next GEMM's A buffer
    attn_mma<<<dim3(SEQ / 128, BTC * NHEADS), 256, ATN_SMEM>>>(Ah);

    {
        int n4b = DMODEL * KDIM / 4;
        splitw_kernel<<<(n4b + 255) / 256, 256>>>(w_out, Bh, Bl, n4b);
    }
    // out = o @ w_out^T + b_out
    gemm_mma<<<dim3(DMODEL / 128, MROWS / 128), 256, GEMM_SMEM>>>(
        Ah, Bh, Bl, out, DMODEL, b_out);
}

// round 8
// speedup vs baseline: 13.3730x; 1.1389x over previous
#include <cuda_runtime.h>
#include <cuda_fp16.h>
#include <math.h>
#include <stdint.h>

// Problem constants
#define BTC    16
#define SEQ    1024
#define DMODEL 768
#define NHEADS 12
#define HDIM   64
#define MROWS  (BTC * SEQ)     // 16384
#define QKVN   (3 * DMODEL)    // 2304
#define KDIM   768

// Scratch (static device globals: allocation-guard safe)
__device__ float g_cos[SEQ * 32];
__device__ float g_sin[SEQ * 32];
__device__ __half g_QKVh[(size_t)MROWS * QKVN];  // qkv hi (rope+scale applied)
__device__ __half g_QKVl[(size_t)MROWS * QKVN];  // qkv lo residual
__device__ __half g_Ah[(size_t)MROWS * KDIM];    // GEMM-A / attention output, fp16
__device__ __half g_Bh[(size_t)QKVN * KDIM];     // weights hi
__device__ __half g_Bl[(size_t)QKVN * KDIM];     // weights lo

// ===========================================================================
// Helpers
// ===========================================================================
__device__ __forceinline__ uint32_t smem_u32(const void* p) {
    uint32_t a;
    asm("{ .reg .u64 t; cvta.to.shared.u64 t, %1; cvt.u32.u64 %0, t; }" : "=r"(a) : "l"(p));
    return a;
}
#define CP16(dst, src) \
    asm volatile("cp.async.cg.shared.global [%0], [%1], 16;" :: "r"(dst), "l"(src))
#define CP_COMMIT() asm volatile("cp.async.commit_group;")
#define CP_WAIT(n)  asm volatile("cp.async.wait_group %0;" :: "n"(n))

#define LDSM4(r, a)                                                             \
    asm volatile("ldmatrix.sync.aligned.m8n8.x4.shared.b16 {%0,%1,%2,%3}, [%4];" \
        : "=r"((r)[0]), "=r"((r)[1]), "=r"((r)[2]), "=r"((r)[3]) : "r"(a))
#define LDSM4T(r, a)                                                            \
    asm volatile("ldmatrix.sync.aligned.m8n8.x4.trans.shared.b16 {%0,%1,%2,%3}, [%4];" \
        : "=r"((r)[0]), "=r"((r)[1]), "=r"((r)[2]), "=r"((r)[3]) : "r"(a))

__device__ __forceinline__ void mma_f16(float* d, const uint32_t* a, const uint32_t* b) {
    asm volatile(
        "mma.sync.aligned.m16n8k16.row.col.f32.f16.f16.f32 "
        "{%0,%1,%2,%3}, {%4,%5,%6,%7}, {%8,%9}, {%0,%1,%2,%3};"
        : "+f"(d[0]), "+f"(d[1]), "+f"(d[2]), "+f"(d[3])
        : "r"(a[0]), "r"(a[1]), "r"(a[2]), "r"(a[3]), "r"(b[0]), "r"(b[1]));
}

__device__ __forceinline__ uint32_t pack_h2(float x, float y) {
    __half2 h = __floats2half2_rn(x, y);
    return *reinterpret_cast<uint32_t*>(&h);
}
__device__ __forceinline__ void split2h(float x, float y, uint32_t& h, uint32_t& l) {
    h = pack_h2(x, y);
    __half2 hv = *reinterpret_cast<__half2*>(&h);
    l = pack_h2(x - __half2float(hv.x), y - __half2float(hv.y));
}

// ===========================================================================
// RoPE table
// ===========================================================================
__global__ void rope_table_kernel() {
    int idx = blockIdx.x * blockDim.x + threadIdx.x;
    if (idx >= SEQ * 32) return;
    int s = idx >> 5, p = idx & 31;
    float pos = (p < 16) ? (float)(s >> 5) : (float)(s & 31);
    int j = p & 15;
    float inv = exp2f(-(float)j * 0.8304820236903231f);
    g_cos[idx] = cosf(pos * inv);
    g_sin[idx] = sinf(pos * inv);
}

// ===========================================================================
// Conversion kernels
// ===========================================================================
__global__ void conv_half_kernel(const float* __restrict__ in,
                                 __half* __restrict__ out, int n4) {
    int i = blockIdx.x * blockDim.x + threadIdx.x;
    if (i >= n4) return;
    float4 v = *(const float4*)(in + (size_t)i * 4);
    *(uint2*)(out + (size_t)i * 4) = make_uint2(pack_h2(v.x, v.y), pack_h2(v.z, v.w));
}

__global__ void splitw_kernel(const float* __restrict__ in,
                              __half* __restrict__ hi,
                              __half* __restrict__ lo, int n4) {
    int i = blockIdx.x * blockDim.x + threadIdx.x;
    if (i >= n4) return;
    float4 v = *(const float4*)(in + (size_t)i * 4);
    uint32_t h0, l0, h1, l1;
    split2h(v.x, v.y, h0, l0);
    split2h(v.z, v.w, h1, l1);
    *(uint2*)(hi + (size_t)i * 4) = make_uint2(h0, h1);
    *(uint2*)(lo + (size_t)i * 4) = make_uint2(l0, l1);
}

// ===========================================================================
// HMMA fp16 2-term GEMM: C = A[M,768] * B[N,768]^T
// FUSE=true  : QKV gemm — epilogue applies RoPE to q/k, scales q by 1/8,
//              splits to fp16 hi/lo planes Ch/Cl.
// FUSE=false : out-proj — epilogue adds bias, writes fp32 C.
// CTA tile 128x128, 8 warps (2m x 4n), warp 64x32, 2 CTAs/SM.
// ===========================================================================
#define CHUNK 64
#define ROWB 144
#define A_TILE (128 * ROWB)
#define STAGE_BYTES (3 * A_TILE)       // 55296
#define OFF_A 0
#define OFF_BH A_TILE
#define OFF_BL (2 * A_TILE)
#define GEMM_SMEM (2 * STAGE_BYTES)    // 110592
#define NCHUNK (KDIM / CHUNK)          // 12

template <bool FUSE>
__global__ __launch_bounds__(256, 2)
void gemm_mma(const __half* __restrict__ Ah,
              const __half* __restrict__ Bh, const __half* __restrict__ Bl,
              float* __restrict__ C, __half* __restrict__ Ch, __half* __restrict__ Cl,
              int N, const float* __restrict__ bias)
{
    extern __shared__ __align__(128) char sm[];
    const int t = threadIdx.x;
    const int wid = t >> 5, lane = t & 31;
    const int wm = wid & 1, wn = wid >> 1;
    const int gid = lane >> 2, tid4 = lane & 3;
    const int bm = blockIdx.y * 128;
    const int bn = blockIdx.x * 128;

    float acc[4][4][4];
#pragma unroll
    for (int i = 0; i < 4; i++)
#pragma unroll
        for (int j = 0; j < 4; j++)
#pragma unroll
            for (int k = 0; k < 4; k++) acc[i][j][k] = 0.0f;

    const uint32_t smb = smem_u32(sm);
    const uint32_t aoff = (uint32_t)((wm * 64 + (lane & 15)) * ROWB + ((lane >> 4) & 1) * 16);
    const uint32_t boff = (uint32_t)((wn * 32 + (lane & 7) + ((lane >> 4) & 1) * 8) * ROWB +
                                     ((lane >> 3) & 1) * 16);

    auto issue_copy = [&](int c) {
        char* dst0 = sm + (c & 1) * STAGE_BYTES;
        const int k0 = c * CHUNK;
#pragma unroll
        for (int i = 0; i < 12; i++) {
            int idx = i * 256 + t;
            int tile = idx >> 10;
            int rem = idx & 1023;
            int row = rem >> 3, g = rem & 7;
            uint32_t d = smem_u32(dst0 + tile * A_TILE + row * ROWB + g * 16);
            const __half* s;
            if (tile == 0)      s = Ah + (size_t)(bm + row) * KDIM + k0 + g * 8;
            else if (tile == 1) s = Bh + (size_t)(bn + row) * KDIM + k0 + g * 8;
            else                s = Bl + (size_t)(bn + row) * KDIM + k0 + g * 8;
            CP16(d, s);
        }
        CP_COMMIT();
    };

    issue_copy(0);

    for (int c = 0; c < NCHUNK; c++) {
        if (c + 1 < NCHUNK) {
            issue_copy(c + 1);
            CP_WAIT(1);
        } else {
            CP_WAIT(0);
        }
        __syncthreads();

        const uint32_t sb = smb + (c & 1) * STAGE_BYTES;

#pragma unroll
        for (int ks = 0; ks < 4; ks++) {
            uint32_t ah[4][4];
#pragma unroll
            for (int mi = 0; mi < 4; mi++) {
                uint32_t a = sb + aoff + mi * (16 * ROWB) + ks * 32;
                LDSM4(ah[mi], a + OFF_A);
            }
            uint32_t t0[4], t1[4], u0[4], u1[4];
            uint32_t b0 = sb + boff + ks * 32;
            uint32_t b1 = b0 + 16 * ROWB;
            LDSM4(t0, b0 + OFF_BH);
            LDSM4(t1, b1 + OFF_BH);
            LDSM4(u0, b0 + OFF_BL);
            LDSM4(u1, b1 + OFF_BL);
            uint32_t bh[4][2] = {{t0[0], t0[1]}, {t0[2], t0[3]},
                                 {t1[0], t1[1]}, {t1[2], t1[3]}};
            uint32_t bl[4][2] = {{u0[0], u0[1]}, {u0[2], u0[3]},
                                 {u1[0], u1[1]}, {u1[2], u1[3]}};
#pragma unroll
            for (int mi = 0; mi < 4; mi++)
#pragma unroll
                for (int ni = 0; ni < 4; ni++) {
                    float* d = acc[mi][ni];
                    mma_f16(d, ah[mi], bh[ni]);
                    mma_f16(d, ah[mi], bl[ni]);
                }
        }
        __syncthreads();
    }

    // epilogue
#pragma unroll
    for (int mi = 0; mi < 4; mi++) {
        int r0 = bm + wm * 64 + mi * 16 + gid;
#pragma unroll
        for (int ni = 0; ni < 4; ni++) {
            int cc = bn + wn * 32 + ni * 8 + tid4 * 2;
            float2 v0 = make_float2(acc[mi][ni][0], acc[mi][ni][1]);
            float2 v1 = make_float2(acc[mi][ni][2], acc[mi][ni][3]);
            if (FUSE) {
                if (cc < 2 * DMODEL) {   // rope on q and k thirds
                    int p = (cc & 63) >> 1;
                    float c0 = g_cos[((r0 & 1023) << 5) + p];
                    float s0 = g_sin[((r0 & 1023) << 5) + p];
                    float c1 = g_cos[(((r0 + 8) & 1023) << 5) + p];
                    float s1 = g_sin[(((r0 + 8) & 1023) << 5) + p];
                    v0 = make_float2(v0.x * c0 - v0.y * s0, v0.y * c0 + v0.x * s0);
                    v1 = make_float2(v1.x * c1 - v1.y * s1, v1.y * c1 + v1.x * s1);
                    if (cc < DMODEL) {   // q: fold softmax scale
                        v0.x *= 0.125f; v0.y *= 0.125f;
                        v1.x *= 0.125f; v1.y *= 0.125f;
                    }
                }
                uint32_t h, l;
                split2h(v0.x, v0.y, h, l);
                *(uint32_t*)&Ch[(size_t)r0 * N + cc] = h;
                *(uint32_t*)&Cl[(size_t)r0 * N + cc] = l;
                split2h(v1.x, v1.y, h, l);
                *(uint32_t*)&Ch[(size_t)(r0 + 8) * N + cc] = h;
                *(uint32_t*)&Cl[(size_t)(r0 + 8) * N + cc] = l;
            } else {
                float2 bv = *(const float2*)&bias[cc];
                v0.x += bv.x; v0.y += bv.y;
                v1.x += bv.x; v1.y += bv.y;
                *(float2*)&C[(size_t)r0 * N + cc]       = v0;
                *(float2*)&C[(size_t)(r0 + 8) * N + cc] = v1;
            }
        }
    }
}

// ===========================================================================
// HMMA fp16 2-term flash attention, cp.async double-buffered, ldmatrix frags.
// grid=(8, 192), block=256 (8 warps), 2 CTAs/SM. CTA: 128 q-rows, kv tiles 64.
// Inputs pre-split fp16 (rope+scale already applied by the QKV GEMM).
// S = Qh*(Kh+Kl); O += Ph*(Vh+Vl) with V fragments via ldmatrix.trans.
// ===========================================================================
#define AP 144
#define KV_TILE (64 * AP)             // 9216
#define SQ  0
#define SSTAGE (128 * AP)             // 18432: stages start after Q
#define ATN_SMEM (SSTAGE + 2 * 4 * KV_TILE)   // 92160

__global__ __launch_bounds__(256, 2)
void attn_mma(__half* __restrict__ Oh)
{
    extern __shared__ __align__(128) char sm[];
    const int bh = blockIdx.y;
    const int bt = bh / NHEADS;
    const int hh = bh % NHEADS;
    const int q0 = blockIdx.x * 128;
    const int t = threadIdx.x;
    const int wid = t >> 5, lane = t & 31;
    const int gid = lane >> 2, tid4 = lane & 3;
    const size_t btS = (size_t)bt * SEQ;
    const uint32_t smb = smem_u32(sm);

    const __half* Qh = g_QKVh;
    const __half* Ql = g_QKVl;   // (unused plane for q; kept for symmetry)
    (void)Ql;

    // ---- issue Q copy (group 0): 128 rows x 64 halves ----
#pragma unroll
    for (int i = 0; i < 4; i++) {
        int idx = t + 256 * i;
        int row = idx >> 3, g = idx & 7;
        uint32_t d = smb + SQ + row * AP + g * 16;
        CP16(d, Qh + (btS + q0 + row) * QKVN + hh * HDIM + g * 8);
    }
    CP_COMMIT();

    // ---- stage copy: KH, KL, VH, VL tiles (2048 chunks) ----
    auto copy_tile = [&](int kt, int st) {
        uint32_t base = smb + SSTAGE + st * (4 * KV_TILE);
        size_t rb = (btS + (size_t)kt * 64);
#pragma unroll
        for (int i = 0; i < 8; i++) {
            int idx = t + 256 * i;
            int tile = idx >> 9;
            int rem = idx & 511;
            int row = rem >> 3, g = rem & 7;
            uint32_t d = base + tile * KV_TILE + row * AP + g * 16;
            const __half* s;
            size_t off = (rb + row) * QKVN + hh * HDIM + g * 8;
            if (tile == 0)      s = g_QKVh + off + DMODEL;
            else if (tile == 1) s = g_QKVl + off + DMODEL;
            else if (tile == 2) s = g_QKVh + off + 2 * DMODEL;
            else                s = g_QKVl + off + 2 * DMODEL;
            CP16(d, s);
        }
        CP_COMMIT();
    };

    copy_tile(0, 0);

    float m0 = -1e30f, m1 = -1e30f, l0s = 0.0f, l1s = 0.0f;
    float o[8][4];
#pragma unroll
    for (int j = 0; j < 8; j++)
#pragma unroll
        for (int k = 0; k < 4; k++) o[j][k] = 0.0f;

    const uint32_t qoff = smb + SQ + (wid * 16 + (lane & 15)) * AP + ((lane >> 4) & 1) * 16;
    const uint32_t kfrag = (uint32_t)(((lane & 7) + ((lane >> 4) & 1) * 8) * AP +
                                      ((lane >> 3) & 1) * 16);
    const uint32_t vfrag = (uint32_t)((lane & 15) * AP + ((lane >> 4) & 1) * 16);

    for (int kt = 0; kt < SEQ / 64; kt++) {
        const int st = kt & 1;
        if (kt + 1 < SEQ / 64) {
            copy_tile(kt + 1, st ^ 1);
            CP_WAIT(1);
        } else {
            CP_WAIT(0);
        }
        __syncthreads();

        const uint32_t skh = smb + SSTAGE + st * (4 * KV_TILE);
        const uint32_t svh = skh + 2 * KV_TILE;

        // ---- S = Q K^T (2-term) ----
        float s[8][4];
#pragma unroll
        for (int j = 0; j < 8; j++)
#pragma unroll
            for (int k = 0; k < 4; k++) s[j][k] = 0.0f;

#pragma unroll
        for (int ks = 0; ks < 4; ks++) {
            uint32_t aq[4];
            LDSM4(aq, qoff + ks * 32);
#pragma unroll
            for (int h4 = 0; h4 < 4; h4++) {
                uint32_t th[4], tl[4];
                uint32_t ka = skh + kfrag + h4 * (16 * AP) + ks * 32;
                LDSM4(th, ka);
                LDSM4(tl, ka + KV_TILE);
                mma_f16(s[h4 * 2],     aq, th + 0);
                mma_f16(s[h4 * 2],     aq, tl + 0);
                mma_f16(s[h4 * 2 + 1], aq, th + 2);
                mma_f16(s[h4 * 2 + 1], aq, tl + 2);
            }
        }

        // ---- online softmax ----
        float mt0 = -1e30f, mt1 = -1e30f;
#pragma unroll
        for (int j = 0; j < 8; j++) {
            mt0 = fmaxf(mt0, fmaxf(s[j][0], s[j][1]));
            mt1 = fmaxf(mt1, fmaxf(s[j][2], s[j][3]));
        }
        mt0 = fmaxf(mt0, __shfl_xor_sync(0xffffffffu, mt0, 1));
        mt0 = fmaxf(mt0, __shfl_xor_sync(0xffffffffu, mt0, 2));
        mt1 = fmaxf(mt1, __shfl_xor_sync(0xffffffffu, mt1, 1));
        mt1 = fmaxf(mt1, __shfl_xor_sync(0xffffffffu, mt1, 2));
        float mn0 = fmaxf(m0, mt0), mn1 = fmaxf(m1, mt1);
        float a0 = __expf(m0 - mn0), a1 = __expf(m1 - mn1);
        m0 = mn0; m1 = mn1;
        float ps0 = 0.0f, ps1 = 0.0f;
#pragma unroll
        for (int j = 0; j < 8; j++) {
            s[j][0] = __expf(s[j][0] - m0);
            s[j][1] = __expf(s[j][1] - m0);
            s[j][2] = __expf(s[j][2] - m1);
            s[j][3] = __expf(s[j][3] - m1);
            ps0 += s[j][0] + s[j][1];
            ps1 += s[j][2] + s[j][3];
        }
        ps0 += __shfl_xor_sync(0xffffffffu, ps0, 1);
        ps0 += __shfl_xor_sync(0xffffffffu, ps0, 2);
        ps1 += __shfl_xor_sync(0xffffffffu, ps1, 1);
        ps1 += __shfl_xor_sync(0xffffffffu, ps1, 2);
        l0s = l0s * a0 + ps0;
        l1s = l1s * a1 + ps1;
#pragma unroll
        for (int j = 0; j < 8; j++) {
            o[j][0] *= a0; o[j][1] *= a0;
            o[j][2] *= a1; o[j][3] *= a1;
        }

        // ---- O += P V (2-term; V frags via ldmatrix.trans) ----
#pragma unroll
        for (int ks = 0; ks < 4; ks++) {
            uint32_t ph[4];
            ph[0] = pack_h2(s[2 * ks][0],     s[2 * ks][1]);
            ph[1] = pack_h2(s[2 * ks][2],     s[2 * ks][3]);
            ph[2] = pack_h2(s[2 * ks + 1][0], s[2 * ks + 1][1]);
            ph[3] = pack_h2(s[2 * ks + 1][2], s[2 * ks + 1][3]);
#pragma unroll
            for (int d4 = 0; d4 < 4; d4++) {
                uint32_t th[4], tl[4];
                uint32_t va = svh + vfrag + ks * (16 * AP) + d4 * 32;
                LDSM4T(th, va);
                LDSM4T(tl, va + KV_TILE);
                mma_f16(o[d4 * 2],     ph, th + 0);
                mma_f16(o[d4 * 2],     ph, tl + 0);
                mma_f16(o[d4 * 2 + 1], ph, th + 2);
                mma_f16(o[d4 * 2 + 1], ph, tl + 2);
            }
        }
        __syncthreads();   // stage reads done before next copy overwrites
    }

    // ---- epilogue: normalize, write single fp16 into out-proj A buffer ----
    const float i0 = 1.0f / l0s, i1 = 1.0f / l1s;
    const size_t r0 = (size_t)(btS + q0 + wid * 16 + gid);
#pragma unroll
    for (int j = 0; j < 8; j++) {
        int col = hh * HDIM + j * 8 + tid4 * 2;
        *(uint32_t*)&Oh[r0 * DMODEL + col]       = pack_h2(o[j][0] * i0, o[j][1] * i0);
        *(uint32_t*)&Oh[(r0 + 8) * DMODEL + col] = pack_h2(o[j][2] * i1, o[j][3] * i1);
    }
}

// ===========================================================================
extern "C" void kernel_launch(void* const* d_in, const int* in_sizes, int n_in,
                              void* d_out, int out_size)
{
    const float* x     = (const float*)d_in[0];
    const float* w_qkv = (const float*)d_in[1];
    const float* w_out = (const float*)d_in[2];
    const float* b_out = (const float*)d_in[3];
    float* out = (float*)d_out;

    __half *Ah, *Bh, *Bl, *QKVh, *QKVl;
    cudaGetSymbolAddress((void**)&Ah, g_Ah);
    cudaGetSymbolAddress((void**)&Bh, g_Bh);
    cudaGetSymbolAddress((void**)&Bl, g_Bl);
    cudaGetSymbolAddress((void**)&QKVh, g_QKVh);
    cudaGetSymbolAddress((void**)&QKVl, g_QKVl);

    cudaFuncSetAttribute(gemm_mma<true>, cudaFuncAttributeMaxDynamicSharedMemorySize, GEMM_SMEM);
    cudaFuncSetAttribute(gemm_mma<false>, cudaFuncAttributeMaxDynamicSharedMemorySize, GEMM_SMEM);
    cudaFuncSetAttribute(attn_mma, cudaFuncAttributeMaxDynamicSharedMemorySize, ATN_SMEM);

    rope_table_kernel<<<(SEQ * 32 + 255) / 256, 256>>>();

    {
        int n4 = MROWS * KDIM / 4;
        conv_half_kernel<<<(n4 + 255) / 256, 256>>>(x, Ah, n4);
        int n4b = QKVN * KDIM / 4;
        splitw_kernel<<<(n4b + 255) / 256, 256>>>(w_qkv, Bh, Bl, n4b);
    }

    // qkv = x @ w_qkv^T, fused rope+scale+split epilogue -> fp16 hi/lo planes
    gemm_mma<true><<<dim3(QKVN / 128, MROWS / 128), 256, GEMM_SMEM>>>(
        Ah, Bh, Bl, nullptr, QKVh, QKVl, QKVN, nullptr);

    // attention (pre-split inputs) -> fp16 A buffer for out-proj
    attn_mma<<<dim3(SEQ / 128, BTC * NHEADS), 256, ATN_SMEM>>>(Ah);

    {
        int n4b = DMODEL * KDIM / 4;
        splitw_kernel<<<(n4b + 255) / 256, 256>>>(w_out, Bh, Bl, n4b);
    }
    // out = o @ w_out^T + b_out
    gemm_mma<false><<<dim3(DMODEL / 128, MROWS / 128), 256, GEMM_SMEM>>>(
        Ah, Bh, Bl, out, nullptr, nullptr, DMODEL, b_out);
}

// round 9
// speedup vs baseline: 21.4708x; 1.6055x over previous
#include <cuda_runtime.h>
#include <cuda_fp16.h>
#include <math.h>
#include <stdint.h>

// Problem constants
#define BTC    16
#define SEQ    1024
#define DMODEL 768
#define NHEADS 12
#define HDIM   64
#define MROWS  (BTC * SEQ)     // 16384
#define QKVN   (3 * DMODEL)    // 2304
#define KDIM   768

// Scratch (static device globals: allocation-guard safe)
__device__ float g_cos[SEQ * 32];
__device__ float g_sin[SEQ * 32];
__device__ __half g_QKV[(size_t)MROWS * QKVN];   // qkv fp16 (rope+scale applied)
__device__ __half g_Ah[(size_t)MROWS * KDIM];    // GEMM-A / attention output, fp16
__device__ __half g_Bh[(size_t)QKVN * KDIM];     // weights fp16

// ===========================================================================
// Helpers
// ===========================================================================
__device__ __forceinline__ uint32_t smem_u32(const void* p) {
    uint32_t a;
    asm("{ .reg .u64 t; cvta.to.shared.u64 t, %1; cvt.u32.u64 %0, t; }" : "=r"(a) : "l"(p));
    return a;
}
#define CP16(dst, src) \
    asm volatile("cp.async.cg.shared.global [%0], [%1], 16;" :: "r"(dst), "l"(src))
#define CP_COMMIT() asm volatile("cp.async.commit_group;")
#define CP_WAIT(n)  asm volatile("cp.async.wait_group %0;" :: "n"(n))

#define LDSM4(r, a)                                                             \
    asm volatile("ldmatrix.sync.aligned.m8n8.x4.shared.b16 {%0,%1,%2,%3}, [%4];" \
        : "=r"((r)[0]), "=r"((r)[1]), "=r"((r)[2]), "=r"((r)[3]) : "r"(a))
#define LDSM4T(r, a)                                                            \
    asm volatile("ldmatrix.sync.aligned.m8n8.x4.trans.shared.b16 {%0,%1,%2,%3}, [%4];" \
        : "=r"((r)[0]), "=r"((r)[1]), "=r"((r)[2]), "=r"((r)[3]) : "r"(a))

__device__ __forceinline__ void mma_f16(float* d, const uint32_t* a, const uint32_t* b) {
    asm volatile(
        "mma.sync.aligned.m16n8k16.row.col.f32.f16.f16.f32 "
        "{%0,%1,%2,%3}, {%4,%5,%6,%7}, {%8,%9}, {%0,%1,%2,%3};"
        : "+f"(d[0]), "+f"(d[1]), "+f"(d[2]), "+f"(d[3])
        : "r"(a[0]), "r"(a[1]), "r"(a[2]), "r"(a[3]), "r"(b[0]), "r"(b[1]));
}

__device__ __forceinline__ uint32_t pack_h2(float x, float y) {
    __half2 h = __floats2half2_rn(x, y);
    return *reinterpret_cast<uint32_t*>(&h);
}

// ===========================================================================
// RoPE table
// ===========================================================================
__global__ void rope_table_kernel() {
    int idx = blockIdx.x * blockDim.x + threadIdx.x;
    if (idx >= SEQ * 32) return;
    int s = idx >> 5, p = idx & 31;
    float pos = (p < 16) ? (float)(s >> 5) : (float)(s & 31);
    int j = p & 15;
    float inv = exp2f(-(float)j * 0.8304820236903231f);
    g_cos[idx] = cosf(pos * inv);
    g_sin[idx] = sinf(pos * inv);
}

// ===========================================================================
// fp32 -> fp16 conversion
// ===========================================================================
__global__ void conv_half_kernel(const float* __restrict__ in,
                                 __half* __restrict__ out, int n4) {
    int i = blockIdx.x * blockDim.x + threadIdx.x;
    if (i >= n4) return;
    float4 v = *(const float4*)(in + (size_t)i * 4);
    *(uint2*)(out + (size_t)i * 4) = make_uint2(pack_h2(v.x, v.y), pack_h2(v.z, v.w));
}

// ===========================================================================
// HMMA fp16 GEMM: C = A[M,768] * B[N,768]^T
// FUSE=true  : QKV gemm — epilogue applies RoPE to q/k, scales q by 1/8,
//              writes fp16 plane Ch.
// FUSE=false : out-proj — epilogue adds bias, writes fp32 C.
// CTA tile 128x128, 8 warps (2m x 4n), warp 64x32, 2 CTAs/SM,
// 3-stage cp.async pipeline.
// ===========================================================================
#define CHUNK 64
#define ROWB 144
#define A_TILE (128 * ROWB)            // 18432
#define STAGE_BYTES (2 * A_TILE)       // 36864: A + B
#define OFF_A 0
#define OFF_B A_TILE
#define GEMM_SMEM (3 * STAGE_BYTES)    // 110592
#define NCHUNK (KDIM / CHUNK)          // 12

template <bool FUSE>
__global__ __launch_bounds__(256, 2)
void gemm_mma(const __half* __restrict__ Ah, const __half* __restrict__ Bh,
              float* __restrict__ C, __half* __restrict__ Ch,
              int N, const float* __restrict__ bias)
{
    extern __shared__ __align__(128) char sm[];
    const int t = threadIdx.x;
    const int wid = t >> 5, lane = t & 31;
    const int wm = wid & 1, wn = wid >> 1;
    const int gid = lane >> 2, tid4 = lane & 3;
    const int bm = blockIdx.y * 128;
    const int bn = blockIdx.x * 128;

    float acc[4][4][4];
#pragma unroll
    for (int i = 0; i < 4; i++)
#pragma unroll
        for (int j = 0; j < 4; j++)
#pragma unroll
            for (int k = 0; k < 4; k++) acc[i][j][k] = 0.0f;

    const uint32_t smb = smem_u32(sm);
    const uint32_t aoff = (uint32_t)((wm * 64 + (lane & 15)) * ROWB + ((lane >> 4) & 1) * 16);
    const uint32_t boff = (uint32_t)((wn * 32 + (lane & 7) + ((lane >> 4) & 1) * 8) * ROWB +
                                     ((lane >> 3) & 1) * 16);

    auto issue_copy = [&](int c) {
        char* dst0 = sm + (c % 3) * STAGE_BYTES;
        const int k0 = c * CHUNK;
#pragma unroll
        for (int i = 0; i < 8; i++) {
            int idx = i * 256 + t;             // 2048 segments of 16B
            int tile = idx >> 10;              // 0=A, 1=B
            int rem = idx & 1023;
            int row = rem >> 3, g = rem & 7;
            uint32_t d = smem_u32(dst0 + tile * A_TILE + row * ROWB + g * 16);
            const __half* s = (tile == 0)
                ? Ah + (size_t)(bm + row) * KDIM + k0 + g * 8
                : Bh + (size_t)(bn + row) * KDIM + k0 + g * 8;
            CP16(d, s);
        }
        CP_COMMIT();
    };

    issue_copy(0);
    issue_copy(1);

    for (int c = 0; c < NCHUNK; c++) {
        if (c + 2 < NCHUNK) issue_copy(c + 2);
        if (c + 2 < NCHUNK)      CP_WAIT(2);
        else if (c + 1 < NCHUNK) CP_WAIT(1);
        else                     CP_WAIT(0);
        __syncthreads();

        const uint32_t sb = smb + (c % 3) * STAGE_BYTES;

#pragma unroll
        for (int ks = 0; ks < 4; ks++) {
            uint32_t ah[4][4];
#pragma unroll
            for (int mi = 0; mi < 4; mi++)
                LDSM4(ah[mi], sb + aoff + mi * (16 * ROWB) + ks * 32 + OFF_A);
            uint32_t t0[4], t1[4];
            uint32_t b0 = sb + boff + ks * 32 + OFF_B;
            LDSM4(t0, b0);
            LDSM4(t1, b0 + 16 * ROWB);
            uint32_t bh[4][2] = {{t0[0], t0[1]}, {t0[2], t0[3]},
                                 {t1[0], t1[1]}, {t1[2], t1[3]}};
#pragma unroll
            for (int mi = 0; mi < 4; mi++)
#pragma unroll
                for (int ni = 0; ni < 4; ni++)
                    mma_f16(acc[mi][ni], ah[mi], bh[ni]);
        }
        __syncthreads();
    }

    // epilogue
#pragma unroll
    for (int mi = 0; mi < 4; mi++) {
        int r0 = bm + wm * 64 + mi * 16 + gid;
#pragma unroll
        for (int ni = 0; ni < 4; ni++) {
            int cc = bn + wn * 32 + ni * 8 + tid4 * 2;
            float2 v0 = make_float2(acc[mi][ni][0], acc[mi][ni][1]);
            float2 v1 = make_float2(acc[mi][ni][2], acc[mi][ni][3]);
            if (FUSE) {
                if (cc < 2 * DMODEL) {   // rope on q and k thirds
                    int p = (cc & 63) >> 1;
                    float c0 = g_cos[((r0 & 1023) << 5) + p];
                    float s0 = g_sin[((r0 & 1023) << 5) + p];
                    float c1 = g_cos[(((r0 + 8) & 1023) << 5) + p];
                    float s1 = g_sin[(((r0 + 8) & 1023) << 5) + p];
                    v0 = make_float2(v0.x * c0 - v0.y * s0, v0.y * c0 + v0.x * s0);
                    v1 = make_float2(v1.x * c1 - v1.y * s1, v1.y * c1 + v1.x * s1);
                    if (cc < DMODEL) {   // q: fold softmax scale
                        v0.x *= 0.125f; v0.y *= 0.125f;
                        v1.x *= 0.125f; v1.y *= 0.125f;
                    }
                }
                *(uint32_t*)&Ch[(size_t)r0 * N + cc]       = pack_h2(v0.x, v0.y);
                *(uint32_t*)&Ch[(size_t)(r0 + 8) * N + cc] = pack_h2(v1.x, v1.y);
            } else {
                float2 bv = *(const float2*)&bias[cc];
                v0.x += bv.x; v0.y += bv.y;
                v1.x += bv.x; v1.y += bv.y;
                *(float2*)&C[(size_t)r0 * N + cc]       = v0;
                *(float2*)&C[(size_t)(r0 + 8) * N + cc] = v1;
            }
        }
    }
}

// ===========================================================================
// HMMA fp16 flash attention, 3-stage cp.async, ldmatrix fragments.
// grid=(8, 192), block=256 (8 warps), 2 CTAs/SM. CTA: 128 q-rows, kv tiles 64.
// All operands single fp16 (rope+scale pre-applied by QKV GEMM epilogue).
// ===========================================================================
#define AP 144
#define KV_TILE (64 * AP)             // 9216
#define SQ  0
#define SSTAGE (128 * AP)             // 18432: stages start after Q
#define AST_BYTES (2 * KV_TILE)       // 18432: K + V
#define ATN_SMEM (SSTAGE + 3 * AST_BYTES)   // 73728

__global__ __launch_bounds__(256, 2)
void attn_mma(__half* __restrict__ Oh)
{
    extern __shared__ __align__(128) char sm[];
    const int bh = blockIdx.y;
    const int bt = bh / NHEADS;
    const int hh = bh % NHEADS;
    const int q0 = blockIdx.x * 128;
    const int t = threadIdx.x;
    const int wid = t >> 5, lane = t & 31;
    const int gid = lane >> 2, tid4 = lane & 3;
    const size_t btS = (size_t)bt * SEQ;
    const uint32_t smb = smem_u32(sm);

    // ---- issue Q copy: 128 rows x 64 halves ----
#pragma unroll
    for (int i = 0; i < 4; i++) {
        int idx = t + 256 * i;
        int row = idx >> 3, g = idx & 7;
        CP16(smb + SQ + row * AP + g * 16,
             g_QKV + (btS + q0 + row) * QKVN + hh * HDIM + g * 8);
    }
    CP_COMMIT();

    // ---- stage copy: K, V tiles (1024 chunks) ----
    auto copy_tile = [&](int kt) {
        uint32_t base = smb + SSTAGE + (kt % 3) * AST_BYTES;
        size_t rb = btS + (size_t)kt * 64;
#pragma unroll
        for (int i = 0; i < 4; i++) {
            int idx = t + 256 * i;
            int tile = idx >> 9;               // 0=K, 1=V
            int rem = idx & 511;
            int row = rem >> 3, g = rem & 7;
            uint32_t d = base + tile * KV_TILE + row * AP + g * 16;
            CP16(d, g_QKV + (rb + row) * QKVN + (1 + tile) * DMODEL + hh * HDIM + g * 8);
        }
        CP_COMMIT();
    };

    copy_tile(0);
    copy_tile(1);

    float m0 = -1e30f, m1 = -1e30f, l0s = 0.0f, l1s = 0.0f;
    float o[8][4];
#pragma unroll
    for (int j = 0; j < 8; j++)
#pragma unroll
        for (int k = 0; k < 4; k++) o[j][k] = 0.0f;

    const uint32_t qoff = smb + SQ + (wid * 16 + (lane & 15)) * AP + ((lane >> 4) & 1) * 16;
    const uint32_t kfrag = (uint32_t)(((lane & 7) + ((lane >> 4) & 1) * 8) * AP +
                                      ((lane >> 3) & 1) * 16);
    const uint32_t vfrag = (uint32_t)((lane & 15) * AP + ((lane >> 4) & 1) * 16);

    for (int kt = 0; kt < SEQ / 64; kt++) {
        if (kt + 2 < SEQ / 64) copy_tile(kt + 2);
        if (kt + 2 < SEQ / 64)      CP_WAIT(2);
        else if (kt + 1 < SEQ / 64) CP_WAIT(1);
        else                        CP_WAIT(0);
        __syncthreads();

        const uint32_t skh = smb + SSTAGE + (kt % 3) * AST_BYTES;
        const uint32_t svh = skh + KV_TILE;

        // ---- S = Q K^T ----
        float s[8][4];
#pragma unroll
        for (int j = 0; j < 8; j++)
#pragma unroll
            for (int k = 0; k < 4; k++) s[j][k] = 0.0f;

#pragma unroll
        for (int ks = 0; ks < 4; ks++) {
            uint32_t aq[4];
            LDSM4(aq, qoff + ks * 32);
#pragma unroll
            for (int h4 = 0; h4 < 4; h4++) {
                uint32_t th[4];
                LDSM4(th, skh + kfrag + h4 * (16 * AP) + ks * 32);
                mma_f16(s[h4 * 2],     aq, th + 0);
                mma_f16(s[h4 * 2 + 1], aq, th + 2);
            }
        }

        // ---- online softmax ----
        float mt0 = -1e30f, mt1 = -1e30f;
#pragma unroll
        for (int j = 0; j < 8; j++) {
            mt0 = fmaxf(mt0, fmaxf(s[j][0], s[j][1]));
            mt1 = fmaxf(mt1, fmaxf(s[j][2], s[j][3]));
        }
        mt0 = fmaxf(mt0, __shfl_xor_sync(0xffffffffu, mt0, 1));
        mt0 = fmaxf(mt0, __shfl_xor_sync(0xffffffffu, mt0, 2));
        mt1 = fmaxf(mt1, __shfl_xor_sync(0xffffffffu, mt1, 1));
        mt1 = fmaxf(mt1, __shfl_xor_sync(0xffffffffu, mt1, 2));
        float mn0 = fmaxf(m0, mt0), mn1 = fmaxf(m1, mt1);
        float a0 = __expf(m0 - mn0), a1 = __expf(m1 - mn1);
        m0 = mn0; m1 = mn1;
        float ps0 = 0.0f, ps1 = 0.0f;
#pragma unroll
        for (int j = 0; j < 8; j++) {
            s[j][0] = __expf(s[j][0] - m0);
            s[j][1] = __expf(s[j][1] - m0);
            s[j][2] = __expf(s[j][2] - m1);
            s[j][3] = __expf(s[j][3] - m1);
            ps0 += s[j][0] + s[j][1];
            ps1 += s[j][2] + s[j][3];
        }
        ps0 += __shfl_xor_sync(0xffffffffu, ps0, 1);
        ps0 += __shfl_xor_sync(0xffffffffu, ps0, 2);
        ps1 += __shfl_xor_sync(0xffffffffu, ps1, 1);
        ps1 += __shfl_xor_sync(0xffffffffu, ps1, 2);
        l0s = l0s * a0 + ps0;
        l1s = l1s * a1 + ps1;
#pragma unroll
        for (int j = 0; j < 8; j++) {
            o[j][0] *= a0; o[j][1] *= a0;
            o[j][2] *= a1; o[j][3] *= a1;
        }

        // ---- O += P V (V frags via ldmatrix.trans) ----
#pragma unroll
        for (int ks = 0; ks < 4; ks++) {
            uint32_t ph[4];
            ph[0] = pack_h2(s[2 * ks][0],     s[2 * ks][1]);
            ph[1] = pack_h2(s[2 * ks][2],     s[2 * ks][3]);
            ph[2] = pack_h2(s[2 * ks + 1][0], s[2 * ks + 1][1]);
            ph[3] = pack_h2(s[2 * ks + 1][2], s[2 * ks + 1][3]);
#pragma unroll
            for (int d4 = 0; d4 < 4; d4++) {
                uint32_t th[4];
                LDSM4T(th, svh + vfrag + ks * (16 * AP) + d4 * 32);
                mma_f16(o[d4 * 2],     ph, th + 0);
                mma_f16(o[d4 * 2 + 1], ph, th + 2);
            }
        }
        __syncthreads();   // stage reads done before next copy overwrites
    }

    // ---- epilogue: normalize, write fp16 into out-proj A buffer ----
    const float i0 = 1.0f / l0s, i1 = 1.0f / l1s;
    const size_t r0 = (size_t)(btS + q0 + wid * 16 + gid);
#pragma unroll
    for (int j = 0; j < 8; j++) {
        int col = hh * HDIM + j * 8 + tid4 * 2;
        *(uint32_t*)&Oh[r0 * DMODEL + col]       = pack_h2(o[j][0] * i0, o[j][1] * i0);
        *(uint32_t*)&Oh[(r0 + 8) * DMODEL + col] = pack_h2(o[j][2] * i1, o[j][3] * i1);
    }
}

// ===========================================================================
extern "C" void kernel_launch(void* const* d_in, const int* in_sizes, int n_in,
                              void* d_out, int out_size)
{
    const float* x     = (const float*)d_in[0];
    const float* w_qkv = (const float*)d_in[1];
    const float* w_out = (const float*)d_in[2];
    const float* b_out = (const float*)d_in[3];
    float* out = (float*)d_out;

    __half *Ah, *Bh, *QKV;
    cudaGetSymbolAddress((void**)&Ah, g_Ah);
    cudaGetSymbolAddress((void**)&Bh, g_Bh);
    cudaGetSymbolAddress((void**)&QKV, g_QKV);

    cudaFuncSetAttribute(gemm_mma<true>, cudaFuncAttributeMaxDynamicSharedMemorySize, GEMM_SMEM);
    cudaFuncSetAttribute(gemm_mma<false>, cudaFuncAttributeMaxDynamicSharedMemorySize, GEMM_SMEM);
    cudaFuncSetAttribute(attn_mma, cudaFuncAttributeMaxDynamicSharedMemorySize, ATN_SMEM);

    rope_table_kernel<<<(SEQ * 32 + 255) / 256, 256>>>();

    {
        int n4 = MROWS * KDIM / 4;
        conv_half_kernel<<<(n4 + 255) / 256, 256>>>(x, Ah, n4);
        int n4b = QKVN * KDIM / 4;
        conv_half_kernel<<<(n4b + 255) / 256, 256>>>(w_qkv, Bh, n4b);
    }

    // qkv = x @ w_qkv^T, fused rope+scale epilogue -> fp16 plane
    gemm_mma<true><<<dim3(QKVN / 128, MROWS / 128), 256, GEMM_SMEM>>>(
        Ah, Bh, nullptr, QKV, QKVN, nullptr);

    // attention (fp16 operands) -> fp16 A buffer for out-proj
    attn_mma<<<dim3(SEQ / 128, BTC * NHEADS), 256, ATN_SMEM>>>(Ah);

    {
        int n4b = DMODEL * KDIM / 4;
        conv_half_kernel<<<(n4b + 255) / 256, 256>>>(w_out, Bh, n4b);
    }
    // out = o @ w_out^T + b_out
    gemm_mma<false><<<dim3(DMODEL / 128, MROWS / 128), 256, GEMM_SMEM>>>(
        Ah, Bh, out, nullptr, DMODEL, b_out);
}

// round 10
// speedup vs baseline: 22.4348x; 1.0449x over previous
#include <cuda_runtime.h>
#include <cuda_fp16.h>
#include <math.h>
#include <stdint.h>

// Problem constants
#define BTC    16
#define SEQ    1024
#define DMODEL 768
#define NHEADS 12
#define HDIM   64
#define MROWS  (BTC * SEQ)     // 16384
#define QKVN   (3 * DMODEL)    // 2304
#define KDIM   768

// Scratch (static device globals: allocation-guard safe)
__device__ float g_cos[SEQ * 32];
__device__ float g_sin[SEQ * 32];
__device__ __half g_QKV[(size_t)MROWS * QKVN];   // qkv fp16 (rope+scale applied)
__device__ __half g_Ah[(size_t)MROWS * KDIM];    // GEMM-A / attention output, fp16
__device__ __half g_Bq[(size_t)QKVN * KDIM];     // w_qkv fp16
__device__ __half g_Bo[(size_t)DMODEL * KDIM];   // w_out fp16

// ===========================================================================
// Helpers
// ===========================================================================
__device__ __forceinline__ uint32_t smem_u32(const void* p) {
    uint32_t a;
    asm("{ .reg .u64 t; cvta.to.shared.u64 t, %1; cvt.u32.u64 %0, t; }" : "=r"(a) : "l"(p));
    return a;
}
#define CP16(dst, src) \
    asm volatile("cp.async.cg.shared.global [%0], [%1], 16;" :: "r"(dst), "l"(src))
#define CP_COMMIT() asm volatile("cp.async.commit_group;")
#define CP_WAIT(n)  asm volatile("cp.async.wait_group %0;" :: "n"(n))

#define LDSM4(r, a)                                                             \
    asm volatile("ldmatrix.sync.aligned.m8n8.x4.shared.b16 {%0,%1,%2,%3}, [%4];" \
        : "=r"((r)[0]), "=r"((r)[1]), "=r"((r)[2]), "=r"((r)[3]) : "r"(a))
#define LDSM4T(r, a)                                                            \
    asm volatile("ldmatrix.sync.aligned.m8n8.x4.trans.shared.b16 {%0,%1,%2,%3}, [%4];" \
        : "=r"((r)[0]), "=r"((r)[1]), "=r"((r)[2]), "=r"((r)[3]) : "r"(a))

__device__ __forceinline__ void mma_f16(float* d, const uint32_t* a, const uint32_t* b) {
    asm volatile(
        "mma.sync.aligned.m16n8k16.row.col.f32.f16.f16.f32 "
        "{%0,%1,%2,%3}, {%4,%5,%6,%7}, {%8,%9}, {%0,%1,%2,%3};"
        : "+f"(d[0]), "+f"(d[1]), "+f"(d[2]), "+f"(d[3])
        : "r"(a[0]), "r"(a[1]), "r"(a[2]), "r"(a[3]), "r"(b[0]), "r"(b[1]));
}

__device__ __forceinline__ uint32_t pack_h2(float x, float y) {
    __half2 h = __floats2half2_rn(x, y);
    return *reinterpret_cast<uint32_t*>(&h);
}

// ===========================================================================
// Prep kernel: rope table + all fp32->fp16 conversions in one launch.
// Block ranges: [0,XB) x->Ah, [XB,XB+WQB) w_qkv->Bq, then w_out->Bo, then rope.
// ===========================================================================
#define XB  (MROWS * KDIM / 4 / 256)            // 12288
#define WQB (QKVN * KDIM / 4 / 256)             // 1728
#define WOB (DMODEL * KDIM / 4 / 256)           // 576
#define RPB (SEQ * 32 / 256)                    // 128
#define PREP_BLOCKS (XB + WQB + WOB + RPB)

__global__ void prep_kernel(const float* __restrict__ x,
                            const float* __restrict__ w_qkv,
                            const float* __restrict__ w_out)
{
    int b = blockIdx.x, t = threadIdx.x;
    if (b < XB + WQB + WOB) {
        const float* in;
        __half* out;
        size_t i;
        if (b < XB)            { in = x;     out = g_Ah; i = (size_t)b * 256 + t; }
        else if (b < XB + WQB) { in = w_qkv; out = g_Bq; i = (size_t)(b - XB) * 256 + t; }
        else                   { in = w_out; out = g_Bo; i = (size_t)(b - XB - WQB) * 256 + t; }
        float4 v = *(const float4*)(in + i * 4);
        *(uint2*)(out + i * 4) = make_uint2(pack_h2(v.x, v.y), pack_h2(v.z, v.w));
    } else {
        int idx = (b - XB - WQB - WOB) * 256 + t;
        int s = idx >> 5, p = idx & 31;
        float pos = (p < 16) ? (float)(s >> 5) : (float)(s & 31);
        int j = p & 15;
        float inv = exp2f(-(float)j * 0.8304820236903231f);
        g_cos[idx] = cosf(pos * inv);
        g_sin[idx] = sinf(pos * inv);
    }
}

// ===========================================================================
// HMMA fp16 GEMM: C = A[M,768] * B[N,768]^T
// FUSE=true  : QKV gemm — epilogue applies RoPE to q/k, scales q by 1/8,
//              writes fp16 plane Ch.
// FUSE=false : out-proj — epilogue adds bias, writes fp32 C.
// CTA tile 128x128, 8 warps (2m x 4n), warp 64x32, 2 CTAs/SM,
// 3-stage cp.async pipeline, ONE sync per chunk, B-fragment prefetch.
// ===========================================================================
#define CHUNK 64
#define ROWB 144
#define A_TILE (128 * ROWB)            // 18432
#define STAGE_BYTES (2 * A_TILE)       // 36864: A + B
#define OFF_A 0
#define OFF_B A_TILE
#define GEMM_SMEM (3 * STAGE_BYTES)    // 110592
#define NCHUNK (KDIM / CHUNK)          // 12

template <bool FUSE>
__global__ __launch_bounds__(256, 2)
void gemm_mma(const __half* __restrict__ Ah, const __half* __restrict__ Bh,
              float* __restrict__ C, __half* __restrict__ Ch,
              int N, const float* __restrict__ bias)
{
    extern __shared__ __align__(128) char sm[];
    const int t = threadIdx.x;
    const int wid = t >> 5, lane = t & 31;
    const int wm = wid & 1, wn = wid >> 1;
    const int gid = lane >> 2, tid4 = lane & 3;
    const int bm = blockIdx.y * 128;
    const int bn = blockIdx.x * 128;

    float acc[4][4][4];
#pragma unroll
    for (int i = 0; i < 4; i++)
#pragma unroll
        for (int j = 0; j < 4; j++)
#pragma unroll
            for (int k = 0; k < 4; k++) acc[i][j][k] = 0.0f;

    const uint32_t smb = smem_u32(sm);
    const uint32_t aoff = (uint32_t)((wm * 64 + (lane & 15)) * ROWB + ((lane >> 4) & 1) * 16);
    const uint32_t boff = (uint32_t)((wn * 32 + (lane & 7) + ((lane >> 4) & 1) * 8) * ROWB +
                                     ((lane >> 3) & 1) * 16);

    auto issue_copy = [&](int c) {
        char* dst0 = sm + (c % 3) * STAGE_BYTES;
        const int k0 = c * CHUNK;
#pragma unroll
        for (int i = 0; i < 8; i++) {
            int idx = i * 256 + t;             // 2048 segments of 16B
            int tile = idx >> 10;              // 0=A, 1=B
            int rem = idx & 1023;
            int row = rem >> 3, g = rem & 7;
            uint32_t d = smem_u32(dst0 + tile * A_TILE + row * ROWB + g * 16);
            const __half* s = (tile == 0)
                ? Ah + (size_t)(bm + row) * KDIM + k0 + g * 8
                : Bh + (size_t)(bn + row) * KDIM + k0 + g * 8;
            CP16(d, s);
        }
        CP_COMMIT();
    };

    issue_copy(0);
    issue_copy(1);

    for (int c = 0; c < NCHUNK; c++) {
        if (c + 1 < NCHUNK) CP_WAIT(1); else CP_WAIT(0);
        __syncthreads();
        if (c + 2 < NCHUNK) issue_copy(c + 2);

        const uint32_t sb = smb + (c % 3) * STAGE_BYTES;

        uint32_t bf[2][8];
        {
            uint32_t b0 = sb + boff + OFF_B;
            LDSM4(bf[0], b0);
            LDSM4(bf[0] + 4, b0 + 16 * ROWB);
        }
#pragma unroll
        for (int ks = 0; ks < 4; ks++) {
            uint32_t ah[4][4];
#pragma unroll
            for (int mi = 0; mi < 4; mi++)
                LDSM4(ah[mi], sb + aoff + mi * (16 * ROWB) + ks * 32 + OFF_A);
            if (ks < 3) {
                uint32_t b0 = sb + boff + (ks + 1) * 32 + OFF_B;
                LDSM4(bf[(ks + 1) & 1], b0);
                LDSM4(bf[(ks + 1) & 1] + 4, b0 + 16 * ROWB);
            }
            const uint32_t* bp = bf[ks & 1];
            uint32_t bh2[4][2] = {{bp[0], bp[1]}, {bp[2], bp[3]},
                                  {bp[4], bp[5]}, {bp[6], bp[7]}};
#pragma unroll
            for (int mi = 0; mi < 4; mi++)
#pragma unroll
                for (int ni = 0; ni < 4; ni++)
                    mma_f16(acc[mi][ni], ah[mi], bh2[ni]);
        }
    }

    // epilogue
#pragma unroll
    for (int mi = 0; mi < 4; mi++) {
        int r0 = bm + wm * 64 + mi * 16 + gid;
#pragma unroll
        for (int ni = 0; ni < 4; ni++) {
            int cc = bn + wn * 32 + ni * 8 + tid4 * 2;
            float2 v0 = make_float2(acc[mi][ni][0], acc[mi][ni][1]);
            float2 v1 = make_float2(acc[mi][ni][2], acc[mi][ni][3]);
            if (FUSE) {
                if (cc < 2 * DMODEL) {   // rope on q and k thirds
                    int p = (cc & 63) >> 1;
                    float c0 = g_cos[((r0 & 1023) << 5) + p];
                    float s0 = g_sin[((r0 & 1023) << 5) + p];
                    float c1 = g_cos[(((r0 + 8) & 1023) << 5) + p];
                    float s1 = g_sin[(((r0 + 8) & 1023) << 5) + p];
                    v0 = make_float2(v0.x * c0 - v0.y * s0, v0.y * c0 + v0.x * s0);
                    v1 = make_float2(v1.x * c1 - v1.y * s1, v1.y * c1 + v1.x * s1);
                    if (cc < DMODEL) {   // q: fold softmax scale
                        v0.x *= 0.125f; v0.y *= 0.125f;
                        v1.x *= 0.125f; v1.y *= 0.125f;
                    }
                }
                *(uint32_t*)&Ch[(size_t)r0 * N + cc]       = pack_h2(v0.x, v0.y);
                *(uint32_t*)&Ch[(size_t)(r0 + 8) * N + cc] = pack_h2(v1.x, v1.y);
            } else {
                float2 bv = *(const float2*)&bias[cc];
                v0.x += bv.x; v0.y += bv.y;
                v1.x += bv.x; v1.y += bv.y;
                *(float2*)&C[(size_t)r0 * N + cc]       = v0;
                *(float2*)&C[(size_t)(r0 + 8) * N + cc] = v1;
            }
        }
    }
}

// ===========================================================================
// HMMA fp16 flash attention, 3-stage cp.async, ldmatrix fragments,
// ONE sync per tile, Q fragments hoisted out of the kv loop.
// grid=(8, 192), block=256 (8 warps), 2 CTAs/SM. CTA: 128 q-rows, kv tiles 64.
// ===========================================================================
#define AP 144
#define KV_TILE (64 * AP)             // 9216
#define SQ  0
#define SSTAGE (128 * AP)             // 18432: stages start after Q
#define AST_BYTES (2 * KV_TILE)       // 18432: K + V
#define ATN_SMEM (SSTAGE + 3 * AST_BYTES)   // 73728
#define NT (SEQ / 64)                 // 16

__global__ __launch_bounds__(256, 2)
void attn_mma(__half* __restrict__ Oh)
{
    extern __shared__ __align__(128) char sm[];
    const int bh = blockIdx.y;
    const int bt = bh / NHEADS;
    const int hh = bh % NHEADS;
    const int q0 = blockIdx.x * 128;
    const int t = threadIdx.x;
    const int wid = t >> 5, lane = t & 31;
    const int gid = lane >> 2, tid4 = lane & 3;
    const size_t btS = (size_t)bt * SEQ;
    const uint32_t smb = smem_u32(sm);

    // ---- issue Q copy: 128 rows x 64 halves ----
#pragma unroll
    for (int i = 0; i < 4; i++) {
        int idx = t + 256 * i;
        int row = idx >> 3, g = idx & 7;
        CP16(smb + SQ + row * AP + g * 16,
             g_QKV + (btS + q0 + row) * QKVN + hh * HDIM + g * 8);
    }
    CP_COMMIT();

    // ---- stage copy: K, V tiles (1024 chunks) ----
    auto copy_tile = [&](int kt) {
        uint32_t base = smb + SSTAGE + (kt % 3) * AST_BYTES;
        size_t rb = btS + (size_t)kt * 64;
#pragma unroll
        for (int i = 0; i < 4; i++) {
            int idx = t + 256 * i;
            int tile = idx >> 9;               // 0=K, 1=V
            int rem = idx & 511;
            int row = rem >> 3, g = rem & 7;
            uint32_t d = base + tile * KV_TILE + row * AP + g * 16;
            CP16(d, g_QKV + (rb + row) * QKVN + (1 + tile) * DMODEL + hh * HDIM + g * 8);
        }
        CP_COMMIT();
    };

    copy_tile(0);
    copy_tile(1);

    // ---- Q frags hoisted: wait for Q group, then LDSM once ----
    CP_WAIT(2);
    __syncthreads();
    const uint32_t qoff = smb + SQ + (wid * 16 + (lane & 15)) * AP + ((lane >> 4) & 1) * 16;
    uint32_t qf[4][4];
#pragma unroll
    for (int ks = 0; ks < 4; ks++)
        LDSM4(qf[ks], qoff + ks * 32);

    float m0 = -1e30f, m1 = -1e30f, l0s = 0.0f, l1s = 0.0f;
    float o[8][4];
#pragma unroll
    for (int j = 0; j < 8; j++)
#pragma unroll
        for (int k = 0; k < 4; k++) o[j][k] = 0.0f;

    const uint32_t kfrag = (uint32_t)(((lane & 7) + ((lane >> 4) & 1) * 8) * AP +
                                      ((lane >> 3) & 1) * 16);
    const uint32_t vfrag = (uint32_t)((lane & 15) * AP + ((lane >> 4) & 1) * 16);

    for (int kt = 0; kt < NT; kt++) {
        if (kt + 1 < NT) CP_WAIT(1); else CP_WAIT(0);
        __syncthreads();
        if (kt + 2 < NT) copy_tile(kt + 2);

        const uint32_t skh = smb + SSTAGE + (kt % 3) * AST_BYTES;
        const uint32_t svh = skh + KV_TILE;

        // ---- S = Q K^T ----
        float s[8][4];
#pragma unroll
        for (int j = 0; j < 8; j++)
#pragma unroll
            for (int k = 0; k < 4; k++) s[j][k] = 0.0f;

#pragma unroll
        for (int ks = 0; ks < 4; ks++) {
#pragma unroll
            for (int h4 = 0; h4 < 4; h4++) {
                uint32_t th[4];
                LDSM4(th, skh + kfrag + h4 * (16 * AP) + ks * 32);
                mma_f16(s[h4 * 2],     qf[ks], th + 0);
                mma_f16(s[h4 * 2 + 1], qf[ks], th + 2);
            }
        }

        // ---- online softmax ----
        float mt0 = -1e30f, mt1 = -1e30f;
#pragma unroll
        for (int j = 0; j < 8; j++) {
            mt0 = fmaxf(mt0, fmaxf(s[j][0], s[j][1]));
            mt1 = fmaxf(mt1, fmaxf(s[j][2], s[j][3]));
        }
        mt0 = fmaxf(mt0, __shfl_xor_sync(0xffffffffu, mt0, 1));
        mt0 = fmaxf(mt0, __shfl_xor_sync(0xffffffffu, mt0, 2));
        mt1 = fmaxf(mt1, __shfl_xor_sync(0xffffffffu, mt1, 1));
        mt1 = fmaxf(mt1, __shfl_xor_sync(0xffffffffu, mt1, 2));
        float mn0 = fmaxf(m0, mt0), mn1 = fmaxf(m1, mt1);
        float a0 = __expf(m0 - mn0), a1 = __expf(m1 - mn1);
        m0 = mn0; m1 = mn1;
        float ps0 = 0.0f, ps1 = 0.0f;
#pragma unroll
        for (int j = 0; j < 8; j++) {
            s[j][0] = __expf(s[j][0] - m0);
            s[j][1] = __expf(s[j][1] - m0);
            s[j][2] = __expf(s[j][2] - m1);
            s[j][3] = __expf(s[j][3] - m1);
            ps0 += s[j][0] + s[j][1];
            ps1 += s[j][2] + s[j][3];
        }
        ps0 += __shfl_xor_sync(0xffffffffu, ps0, 1);
        ps0 += __shfl_xor_sync(0xffffffffu, ps0, 2);
        ps1 += __shfl_xor_sync(0xffffffffu, ps1, 1);
        ps1 += __shfl_xor_sync(0xffffffffu, ps1, 2);
        l0s = l0s * a0 + ps0;
        l1s = l1s * a1 + ps1;
#pragma unroll
        for (int j = 0; j < 8; j++) {
            o[j][0] *= a0; o[j][1] *= a0;
            o[j][2] *= a1; o[j][3] *= a1;
        }

        // ---- O += P V (V frags via ldmatrix.trans) ----
#pragma unroll
        for (int ks = 0; ks < 4; ks++) {
            uint32_t ph[4];
            ph[0] = pack_h2(s[2 * ks][0],     s[2 * ks][1]);
            ph[1] = pack_h2(s[2 * ks][2],     s[2 * ks][3]);
            ph[2] = pack_h2(s[2 * ks + 1][0], s[2 * ks + 1][1]);
            ph[3] = pack_h2(s[2 * ks + 1][2], s[2 * ks + 1][3]);
#pragma unroll
            for (int d4 = 0; d4 < 4; d4++) {
                uint32_t th[4];
                LDSM4T(th, svh + vfrag + ks * (16 * AP) + d4 * 32);
                mma_f16(o[d4 * 2],     ph, th + 0);
                mma_f16(o[d4 * 2 + 1], ph, th + 2);
            }
        }
    }

    // ---- epilogue: normalize, write fp16 into out-proj A buffer ----
    const float i0 = 1.0f / l0s, i1 = 1.0f / l1s;
    const size_t r0 = (size_t)(btS + q0 + wid * 16 + gid);
#pragma unroll
    for (int j = 0; j < 8; j++) {
        int col = hh * HDIM + j * 8 + tid4 * 2;
        *(uint32_t*)&Oh[r0 * DMODEL + col]       = pack_h2(o[j][0] * i0, o[j][1] * i0);
        *(uint32_t*)&Oh[(r0 + 8) * DMODEL + col] = pack_h2(o[j][2] * i1, o[j][3] * i1);
    }
}

// ===========================================================================
extern "C" void kernel_launch(void* const* d_in, const int* in_sizes, int n_in,
                              void* d_out, int out_size)
{
    const float* x     = (const float*)d_in[0];
    const float* w_qkv = (const float*)d_in[1];
    const float* w_out = (const float*)d_in[2];
    const float* b_out = (const float*)d_in[3];
    float* out = (float*)d_out;

    __half *Ah, *Bq, *Bo, *QKV;
    cudaGetSymbolAddress((void**)&Ah, g_Ah);
    cudaGetSymbolAddress((void**)&Bq, g_Bq);
    cudaGetSymbolAddress((void**)&Bo, g_Bo);
    cudaGetSymbolAddress((void**)&QKV, g_QKV);

    cudaFuncSetAttribute(gemm_mma<true>, cudaFuncAttributeMaxDynamicSharedMemorySize, GEMM_SMEM);
    cudaFuncSetAttribute(gemm_mma<false>, cudaFuncAttributeMaxDynamicSharedMemorySize, GEMM_SMEM);
    cudaFuncSetAttribute(attn_mma, cudaFuncAttributeMaxDynamicSharedMemorySize, ATN_SMEM);

    // all conversions + rope table, one launch
    prep_kernel<<<PREP_BLOCKS, 256>>>(x, w_qkv, w_out);

    // qkv = x @ w_qkv^T, fused rope+scale epilogue -> fp16 plane
    gemm_mma<true><<<dim3(QKVN / 128, MROWS / 128), 256, GEMM_SMEM>>>(
        Ah, Bq, nullptr, QKV, QKVN, nullptr);

    // attention (fp16 operands) -> fp16 A buffer for out-proj
    attn_mma<<<dim3(SEQ / 128, BTC * NHEADS), 256, ATN_SMEM>>>(Ah);

    // out = o @ w_out^T + b_out
    gemm_mma<false><<<dim3(DMODEL / 128, MROWS / 128), 256, GEMM_SMEM>>>(
        Ah, Bo, out, nullptr, DMODEL, b_out);
}